// round 11
// baseline (speedup 1.0000x reference)
#include <cuda_runtime.h>
#include <cuda_fp16.h>
#include <math.h>
#include <stdint.h>

#define SEQ    1024
#define DMODEL 1024
#define NQK    32
#define DQK    32
#define NOV    2048
#define BATCH  2
#define VKV    16
#define KVLEN  (SEQ + VKV)   /* 1040 */
#define KVPAD  1088          /* padded kv pitch for g_vh */
#define RATIO  (NOV / NQK)   /* 64 */
#define FULLM  0xFFFFFFFFu

// ---------------- scratch (static device globals; no allocation) ----------------
__device__ __half g_qh[(size_t)BATCH * NQK * SEQ   * DQK];   // [b][h][s][d], pre-scaled 1/sqrt(32)
__device__ __half g_kh[(size_t)BATCH * NQK * KVLEN * DQK];   // [b][h][kv][d]
__device__ __half g_vh[(size_t)BATCH * NOV * KVPAD];         // [b][n][kv]  (transposed, padded)
__device__ __half g_zh[(size_t)BATCH * SEQ * NOV];           // [bs][n]
__device__ __half g_xh[(size_t)BATCH * SEQ * DMODEL];        // resid as half [m][k]
__device__ __half g_bh[(size_t)4096 * DMODEL];               // [Wq^T | Wk^T | Wv] as [n][k]
__device__ __half g_woh[(size_t)DMODEL * NOV];               // Wo^T as [n][k]
__device__ float  g_sin[SEQ * 16];
__device__ float  g_cos[SEQ * 16];

// ---------------- helpers ----------------
__device__ __forceinline__ uint32_t packh2(float lo, float hi) {
    __half2 h = __floats2half2_rn(lo, hi);
    return *(uint32_t*)&h;
}
__device__ __forceinline__ void mma16(float4& d, const uint32_t* a, const uint32_t* b) {
    asm volatile(
        "mma.sync.aligned.m16n8k16.row.col.f32.f16.f16.f32 "
        "{%0,%1,%2,%3}, {%4,%5,%6,%7}, {%8,%9}, {%0,%1,%2,%3};\n"
        : "+f"(d.x), "+f"(d.y), "+f"(d.z), "+f"(d.w)
        : "r"(a[0]), "r"(a[1]), "r"(a[2]), "r"(a[3]), "r"(b[0]), "r"(b[1]));
}
__device__ __forceinline__ void cp_async16(uint32_t dst_smem, const void* src, int src_bytes) {
    asm volatile("cp.async.cg.shared.global [%0], [%1], 16, %2;"
                 :: "r"(dst_smem), "l"(src), "r"(src_bytes));
}

// ---------------- setup: rotary table + virtual k/v + V padding ----------------
__global__ void setup_kernel(const float* __restrict__ vk, const float* __restrict__ vv) {
    int i = blockIdx.x * blockDim.x + threadIdx.x;
    if (i < SEQ * 16) {
        int pos = i >> 4, jm = i & 15;
        float freq = powf(10000.0f, (float)jm * (1.0f / 16.0f));
        float ang = (float)pos / freq;
        g_sin[i] = sinf(ang);
        g_cos[i] = cosf(ang);
    }
    if (i < BATCH * NQK * VKV * DQK) {
        int d  = i & 31;
        int tt = (i >> 5) & 15;
        int h  = (i >> 9) & 31;
        int b  = i >> 14;
        g_kh[(((size_t)b * NQK + h) * KVLEN + SEQ + tt) * DQK + d] =
            __float2half(vk[((size_t)tt * NQK + h) * DQK + d]);
    }
    if (i < BATCH * NOV * 64) {
        int c = 1024 + (i & 63);
        int n = (i >> 6) & 2047;
        int b = i >> 17;
        float val = (c < KVLEN) ? vv[(size_t)(c - SEQ) * NOV + n] : 0.f;
        g_vh[((size_t)b * NOV + n) * KVPAD + c] = __float2half(val);
    }
}

// ---------------- elementwise converts: resid -> g_xh, Wv -> g_bh rows 2048.. -------
__global__ void __launch_bounds__(256) convert_kernel(
    const float* __restrict__ resid, const float* __restrict__ Wv)
{
    int i = blockIdx.x * blockDim.x + threadIdx.x;   // 262144 threads, 8 elems each
    size_t base = (size_t)i * 8;
    float4 a0 = *(const float4*)(resid + base);
    float4 a1 = *(const float4*)(resid + base + 4);
    *(uint4*)&g_xh[base] = make_uint4(packh2(a0.x, a0.y), packh2(a0.z, a0.w),
                                      packh2(a1.x, a1.y), packh2(a1.z, a1.w));
    float4 b0 = *(const float4*)(Wv + base);
    float4 b1 = *(const float4*)(Wv + base + 4);
    *(uint4*)&g_bh[(size_t)2048 * DMODEL + base] =
        make_uint4(packh2(b0.x, b0.y), packh2(b0.z, b0.w),
                   packh2(b1.x, b1.y), packh2(b1.z, b1.w));
}

// ---------------- tiled transpose: Wq/Wk [h][m][d] -> g_bh [h*32+d][m] ----------------
__global__ void transpose_qk_kernel(const float* __restrict__ Wq,
                                    const float* __restrict__ Wk)
{
    __shared__ float sm[32][33];
    int m0 = blockIdx.x * 32;
    int h  = blockIdx.y;
    int z  = blockIdx.z;
    const float* W = z ? Wk : Wq;
    int tx = threadIdx.x, ty = threadIdx.y;
    sm[ty][tx] = W[((size_t)h * 1024 + m0 + ty) * 32 + tx];
    __syncthreads();
    g_bh[((size_t)z * 1024 + h * 32 + ty) * DMODEL + m0 + tx] = __float2half(sm[tx][ty]);
}

// ---------------- tiled transpose: Wo [k][n] -> g_woh [n][k] ----------------
__global__ void transpose_wo_kernel(const float* __restrict__ Wo)
{
    __shared__ float sm[32][33];
    int k0 = blockIdx.x * 32;
    int n0 = blockIdx.y * 32;
    int tx = threadIdx.x, ty = threadIdx.y;
    sm[ty][tx] = Wo[(size_t)(k0 + ty) * DMODEL + n0 + tx];
    __syncthreads();
    g_woh[(size_t)(n0 + ty) * NOV + k0 + tx] = __float2half(sm[tx][ty]);
}

// ---------------- fused QKV GEMM (fp16 mma, cp.async double-buffered) ----------------
// Uniform mainloop: C[2048 x 4096] = g_xh @ g_bh^T. Regions only in epilogue.
// BM=128, BN=128, BK=32, grid (32 n-tiles, 16 m-tiles), 8 warps.
__global__ void __launch_bounds__(256, 2) qkv_gemm_kernel(
    const float* __restrict__ bq, const float* __restrict__ bk,
    const float* __restrict__ bv)
{
    extern __shared__ uint32_t dsm[];            // pipeline 40960 B; epilogue stage 67584 B
    uint32_t* As0 = dsm;                         // [2][128*20] words
    uint32_t* Bs0 = dsm + 2 * 128 * 20;          // [2][128*20]
    float (*Cs)[132] = (float(*)[132])dsm;       // f32 stage alias (Q/K epilogue)
    __half* Ch = (__half*)dsm;                   // half stage alias (V epilogue)

    int nt = blockIdx.x;
    int n0 = nt * 128;
    int r0 = blockIdx.y * 128;
    int region = (nt < 8) ? 0 : (nt < 16) ? 1 : 2;
    int cb = (region == 0) ? n0 : (region == 1) ? n0 - 1024 : n0 - 2048;
    int hbase = cb >> 5;

    int t = threadIdx.x, w = t >> 5, lane = t & 31;
    int g = lane >> 2, tg = lane & 3;
    int wm = w >> 1, wn = w & 1;

    float4 acc[2][8];
    #pragma unroll
    for (int i = 0; i < 2; i++)
        #pragma unroll
        for (int j = 0; j < 8; j++) acc[i][j] = make_float4(0.f, 0.f, 0.f, 0.f);

    const __half* Abase = g_xh + (size_t)r0 * DMODEL;
    const __half* Bbase = g_bh + (size_t)n0 * DMODEL;

    auto issue = [&](int kt) {
        int k0 = kt * 32;
        uint32_t* A = As0 + (kt & 1) * (128 * 20);
        uint32_t* B = Bs0 + (kt & 1) * (128 * 20);
        #pragma unroll
        for (int i = 0; i < 2; i++) {
            int idx = t + i * 256;
            int row = idx >> 2, seg = idx & 3;
            uint32_t da = (uint32_t)__cvta_generic_to_shared(&A[row * 20 + seg * 4]);
            cp_async16(da, Abase + (size_t)row * DMODEL + k0 + seg * 8, 16);
            uint32_t db = (uint32_t)__cvta_generic_to_shared(&B[row * 20 + seg * 4]);
            cp_async16(db, Bbase + (size_t)row * DMODEL + k0 + seg * 8, 16);
        }
        asm volatile("cp.async.commit_group;" ::: "memory");
    };

    issue(0);
    for (int kt = 0; kt < 32; kt++) {
        if (kt + 1 < 32) {
            issue(kt + 1);
            asm volatile("cp.async.wait_group 1;" ::: "memory");
        } else {
            asm volatile("cp.async.wait_group 0;" ::: "memory");
        }
        __syncthreads();

        uint32_t* A = As0 + (kt & 1) * (128 * 20);
        uint32_t* B = Bs0 + (kt & 1) * (128 * 20);
        #pragma unroll
        for (int kb = 0; kb < 2; kb++) {
            uint32_t af[2][4];
            #pragma unroll
            for (int i = 0; i < 2; i++) {
                int rm = wm * 32 + i * 16;
                af[i][0] = A[(rm + g    ) * 20 + 8 * kb + tg];
                af[i][1] = A[(rm + g + 8) * 20 + 8 * kb + tg];
                af[i][2] = A[(rm + g    ) * 20 + 8 * kb + 4 + tg];
                af[i][3] = A[(rm + g + 8) * 20 + 8 * kb + 4 + tg];
            }
            #pragma unroll
            for (int j = 0; j < 8; j++) {
                int cn = wn * 64 + j * 8 + g;
                uint32_t bf[2] = { B[cn * 20 + 8 * kb + tg], B[cn * 20 + 8 * kb + 4 + tg] };
                mma16(acc[0][j], af[0], bf);
                mma16(acc[1][j], af[1], bf);
            }
        }
        __syncthreads();
    }

    if (region == 2) {
        // ---- V epilogue: bias + transpose-stage in smem, coalesced half STG ----
        int nv0 = cb;
        #pragma unroll
        for (int i = 0; i < 2; i++) {
            int rl = wm * 32 + i * 16 + g;
            #pragma unroll
            for (int j = 0; j < 8; j++) {
                int n = wn * 64 + j * 8 + tg * 2;
                float2 bvv = *(const float2*)(bv + nv0 + n);
                Ch[(size_t)n       * 136 + rl    ] = __float2half(acc[i][j].x + bvv.x);
                Ch[(size_t)(n + 1) * 136 + rl    ] = __float2half(acc[i][j].y + bvv.y);
                Ch[(size_t)n       * 136 + rl + 8] = __float2half(acc[i][j].z + bvv.x);
                Ch[(size_t)(n + 1) * 136 + rl + 8] = __float2half(acc[i][j].w + bvv.y);
            }
        }
        __syncthreads();
        int b = r0 >> 10, s0 = r0 & 1023;
        #pragma unroll
        for (int p = 0; p < 8; p++) {
            int idx = t + p * 256;
            int n = idx >> 4, c8 = (idx & 15) * 8;
            uint4 v = *(uint4*)&Ch[(size_t)n * 136 + c8];
            *(uint4*)&g_vh[((size_t)b * NOV + nv0 + n) * KVPAD + s0 + c8] = v;
        }
    } else {
        // ---- Q/K epilogue: bias stage + rotary scatter ----
        const float* bias = (region == 0) ? bq : bk;
        #pragma unroll
        for (int i = 0; i < 2; i++) {
            int rr = wm * 32 + i * 16 + g;
            #pragma unroll
            for (int j = 0; j < 8; j++) {
                int c = wn * 64 + j * 8 + tg * 2;
                float b0 = bias[cb + c];
                float b1 = bias[cb + c + 1];
                Cs[rr    ][c    ] = acc[i][j].x + b0;
                Cs[rr    ][c + 1] = acc[i][j].y + b1;
                Cs[rr + 8][c    ] = acc[i][j].z + b0;
                Cs[rr + 8][c + 1] = acc[i][j].w + b1;
            }
        }
        __syncthreads();

        const float invscale = 0.17677669529663687f;   // 1/sqrt(32)
        float sc = (region == 0) ? invscale : 1.f;
        #pragma unroll
        for (int p = 0; p < 2; p++) {
            int idx = t + p * 256;
            int r = idx >> 2, hh = idx & 3;
            int grow = r0 + r;
            int bb = grow >> 10, pos = grow & 1023;
            int h = hbase + hh;
            const float* base = &Cs[r][hh * 32];
            __half* dst = (region == 0)
                ? g_qh + (((size_t)bb * NQK + h) * SEQ   + pos) * DQK
                : g_kh + (((size_t)bb * NQK + h) * KVLEN + pos) * DQK;
            #pragma unroll
            for (int c = 0; c < 32; c++) {
                float val  = base[c];
                float flip = (c < 16) ? -base[c + 16] : base[c - 16];
                int jm = c & 15;
                float sn = g_sin[pos * 16 + jm];
                float cs = g_cos[pos * 16 + jm];
                dst[c] = __float2half((val * cs + flip * sn) * sc);
            }
        }
    }
}

// ---------------- attention: fp16 mma flash, cp.async double-buffered (unchanged) ----
__global__ void __launch_bounds__(256, 2) attn_mma_kernel()
{
    extern __shared__ uint32_t smem[];
    uint32_t* Kb0 = smem;                  // per buffer 64*20 = 1280 words
    uint32_t* Vb0 = smem + 2 * 1280;       // per buffer 64*36 = 2304 words

    int qt = 7 - blockIdx.x;
    int h = blockIdx.y, b = blockIdx.z;
    int i0 = qt * 128;
    int t = threadIdx.x, w = t >> 5, lane = t & 31;
    int g = lane >> 2, tg = lane & 3;

    const __half* kbp = g_kh + ((size_t)b * NQK + h) * KVLEN * DQK;
    const __half* vbp = g_vh + ((size_t)b * NOV + h * RATIO) * KVPAD;

    uint32_t qf[2][4];
    {
        const __half* qb = g_qh + (((size_t)b * NQK + h) * SEQ + i0 + w * 16) * DQK;
        #pragma unroll
        for (int kb = 0; kb < 2; kb++) {
            qf[kb][0] = *(const uint32_t*)(qb + (size_t)g       * DQK + kb * 16 + 2 * tg);
            qf[kb][1] = *(const uint32_t*)(qb + (size_t)(g + 8) * DQK + kb * 16 + 2 * tg);
            qf[kb][2] = *(const uint32_t*)(qb + (size_t)g       * DQK + kb * 16 + 8 + 2 * tg);
            qf[kb][3] = *(const uint32_t*)(qb + (size_t)(g + 8) * DQK + kb * 16 + 8 + 2 * tg);
        }
    }

    float m_lo = -INFINITY, m_hi = -INFINITY, l_lo = 0.f, l_hi = 0.f;
    float4 z[8];
    #pragma unroll
    for (int j = 0; j < 8; j++) z[j] = make_float4(0.f, 0.f, 0.f, 0.f);

    int row_lo = i0 + w * 16 + g;
    int row_hi = row_lo + 8;
    int warp_min_row = i0 + w * 16;

    int jlim = i0 + 128 + VKV;
    if (jlim > KVLEN) jlim = KVLEN;
    int nch = (jlim + 63) >> 6;

    auto issue = [&](int ch) {
        int kv0 = ch << 6;
        uint32_t* K = Kb0 + (ch & 1) * 1280;
        uint32_t* V = Vb0 + (ch & 1) * 2304;
        {
            int row = t >> 2, seg = t & 3;
            int gj = kv0 + row;
            int cg2 = gj < KVLEN ? gj : KVLEN - 1;
            uint32_t dst = (uint32_t)__cvta_generic_to_shared(&K[row * 20 + seg * 4]);
            cp_async16(dst, kbp + (size_t)cg2 * DQK + seg * 8, gj < KVLEN ? 16 : 0);
        }
        #pragma unroll
        for (int i = 0; i < 2; i++) {
            int idx = t + i * 256;
            int row = idx >> 3, seg = idx & 7;
            uint32_t dst = (uint32_t)__cvta_generic_to_shared(&V[row * 36 + seg * 4]);
            cp_async16(dst, vbp + (size_t)row * KVPAD + kv0 + seg * 8, 16);
        }
        asm volatile("cp.async.commit_group;" ::: "memory");
    };

    issue(0);

    for (int ch = 0; ch < nch; ch++) {
        int kv0 = ch << 6;
        if (ch + 1 < nch) {
            issue(ch + 1);
            asm volatile("cp.async.wait_group 1;" ::: "memory");
        } else {
            asm volatile("cp.async.wait_group 0;" ::: "memory");
        }
        __syncthreads();

        uint32_t* K = Kb0 + (ch & 1) * 1280;
        uint32_t* V = Vb0 + (ch & 1) * 2304;

        float4 s[8];
        #pragma unroll
        for (int j = 0; j < 8; j++) s[j] = make_float4(0.f, 0.f, 0.f, 0.f);
        #pragma unroll
        for (int kb = 0; kb < 2; kb++) {
            #pragma unroll
            for (int j = 0; j < 8; j++) {
                int cn = j * 8 + g;
                uint32_t bf[2] = { K[cn * 20 + 8 * kb + tg], K[cn * 20 + 8 * kb + 4 + tg] };
                mma16(s[j], qf[kb], bf);
            }
        }

        if (kv0 + 63 > warp_min_row + VKV || kv0 + 63 >= KVLEN) {
            #pragma unroll
            for (int j = 0; j < 8; j++) {
                int c0 = kv0 + j * 8 + 2 * tg;
                int c1 = c0 + 1;
                s[j].x = (c0 <= row_lo + VKV && c0 < KVLEN) ? s[j].x : -INFINITY;
                s[j].y = (c1 <= row_lo + VKV && c1 < KVLEN) ? s[j].y : -INFINITY;
                s[j].z = (c0 <= row_hi + VKV && c0 < KVLEN) ? s[j].z : -INFINITY;
                s[j].w = (c1 <= row_hi + VKV && c1 < KVLEN) ? s[j].w : -INFINITY;
            }
        }

        float mx_lo = -INFINITY, mx_hi = -INFINITY;
        #pragma unroll
        for (int j = 0; j < 8; j++) {
            mx_lo = fmaxf(mx_lo, fmaxf(s[j].x, s[j].y));
            mx_hi = fmaxf(mx_hi, fmaxf(s[j].z, s[j].w));
        }
        mx_lo = fmaxf(mx_lo, __shfl_xor_sync(FULLM, mx_lo, 1));
        mx_lo = fmaxf(mx_lo, __shfl_xor_sync(FULLM, mx_lo, 2));
        mx_hi = fmaxf(mx_hi, __shfl_xor_sync(FULLM, mx_hi, 1));
        mx_hi = fmaxf(mx_hi, __shfl_xor_sync(FULLM, mx_hi, 2));
        float mn_lo = fmaxf(m_lo, mx_lo);
        float mn_hi = fmaxf(m_hi, mx_hi);
        float corr_lo = __expf(m_lo - mn_lo);
        float corr_hi = __expf(m_hi - mn_hi);

        float ps_lo = 0.f, ps_hi = 0.f;
        #pragma unroll
        for (int j = 0; j < 8; j++) {
            s[j].x = __expf(s[j].x - mn_lo);
            s[j].y = __expf(s[j].y - mn_lo);
            s[j].z = __expf(s[j].z - mn_hi);
            s[j].w = __expf(s[j].w - mn_hi);
            ps_lo += s[j].x + s[j].y;
            ps_hi += s[j].z + s[j].w;
        }
        ps_lo += __shfl_xor_sync(FULLM, ps_lo, 1);
        ps_lo += __shfl_xor_sync(FULLM, ps_lo, 2);
        ps_hi += __shfl_xor_sync(FULLM, ps_hi, 1);
        ps_hi += __shfl_xor_sync(FULLM, ps_hi, 2);
        l_lo = l_lo * corr_lo + ps_lo;
        l_hi = l_hi * corr_hi + ps_hi;
        m_lo = mn_lo; m_hi = mn_hi;
        #pragma unroll
        for (int j = 0; j < 8; j++) {
            z[j].x *= corr_lo; z[j].y *= corr_lo;
            z[j].z *= corr_hi; z[j].w *= corr_hi;
        }

        #pragma unroll
        for (int kb = 0; kb < 4; kb++) {
            uint32_t af[4];
            af[0] = packh2(s[2 * kb].x,     s[2 * kb].y);
            af[1] = packh2(s[2 * kb].z,     s[2 * kb].w);
            af[2] = packh2(s[2 * kb + 1].x, s[2 * kb + 1].y);
            af[3] = packh2(s[2 * kb + 1].z, s[2 * kb + 1].w);
            #pragma unroll
            for (int j = 0; j < 8; j++) {
                int cn = j * 8 + g;
                uint32_t bf[2] = { V[cn * 36 + 8 * kb + tg], V[cn * 36 + 8 * kb + 4 + tg] };
                mma16(z[j], af, bf);
            }
        }
        __syncthreads();
    }

    float li_lo = 1.f / l_lo;
    float li_hi = 1.f / l_hi;
    __half* zlo = g_zh + ((size_t)b * SEQ + row_lo) * NOV + h * RATIO;
    __half* zhi = g_zh + ((size_t)b * SEQ + row_hi) * NOV + h * RATIO;
    #pragma unroll
    for (int j = 0; j < 8; j++) {
        int col = j * 8 + 2 * tg;
        *(uint32_t*)&zlo[col] = packh2(z[j].x * li_lo, z[j].y * li_lo);
        *(uint32_t*)&zhi[col] = packh2(z[j].z * li_hi, z[j].w * li_hi);
    }
}

// ---------------- output GEMM (fp16 mma, cp.async): BM=64, BN=128, grid (8,32) ----------
__global__ void __launch_bounds__(256, 2) out_gemm_kernel(float* __restrict__ out)
{
    extern __shared__ uint32_t dsm[];
    uint32_t* As0 = dsm;                  // [2][64*20] words
    uint32_t* Bs0 = dsm + 2 * 64 * 20;    // [2][128*20]

    int n0 = blockIdx.x * 128, r0 = blockIdx.y * 64;
    int t = threadIdx.x;
    int w = t >> 5, lane = t & 31;
    int g = lane >> 2, tg = lane & 3;
    int wm = w >> 1, wn = w & 1;

    float4 acc[8];
    #pragma unroll
    for (int j = 0; j < 8; j++) acc[j] = make_float4(0.f, 0.f, 0.f, 0.f);

    const __half* Abase = g_zh + (size_t)r0 * NOV;
    const __half* Bbase = g_woh + (size_t)n0 * NOV;

    auto issue = [&](int kt) {
        int k0 = kt * 32;
        uint32_t* A = As0 + (kt & 1) * (64 * 20);
        uint32_t* B = Bs0 + (kt & 1) * (128 * 20);
        {
            int row = t >> 2, seg = t & 3;
            uint32_t da = (uint32_t)__cvta_generic_to_shared(&A[row * 20 + seg * 4]);
            cp_async16(da, Abase + (size_t)row * NOV + k0 + seg * 8, 16);
        }
        #pragma unroll
        for (int i = 0; i < 2; i++) {
            int idx = t + i * 256;
            int row = idx >> 2, seg = idx & 3;
            uint32_t db = (uint32_t)__cvta_generic_to_shared(&B[row * 20 + seg * 4]);
            cp_async16(db, Bbase + (size_t)row * NOV + k0 + seg * 8, 16);
        }
        asm volatile("cp.async.commit_group;" ::: "memory");
    };

    issue(0);
    for (int kt = 0; kt < 64; kt++) {
        if (kt + 1 < 64) {
            issue(kt + 1);
            asm volatile("cp.async.wait_group 1;" ::: "memory");
        } else {
            asm volatile("cp.async.wait_group 0;" ::: "memory");
        }
        __syncthreads();

        uint32_t* A = As0 + (kt & 1) * (64 * 20);
        uint32_t* B = Bs0 + (kt & 1) * (128 * 20);
        #pragma unroll
        for (int kb = 0; kb < 2; kb++) {
            uint32_t af[4];
            int rm = wm * 16;
            af[0] = A[(rm + g    ) * 20 + 8 * kb + tg];
            af[1] = A[(rm + g + 8) * 20 + 8 * kb + tg];
            af[2] = A[(rm + g    ) * 20 + 8 * kb + 4 + tg];
            af[3] = A[(rm + g + 8) * 20 + 8 * kb + 4 + tg];
            #pragma unroll
            for (int j = 0; j < 8; j++) {
                int cn = wn * 64 + j * 8 + g;
                uint32_t bf[2] = { B[cn * 20 + 8 * kb + tg], B[cn * 20 + 8 * kb + 4 + tg] };
                mma16(acc[j], af, bf);
            }
        }
        __syncthreads();
    }

    int row0 = r0 + wm * 16 + g;
    #pragma unroll
    for (int j = 0; j < 8; j++) {
        int n = n0 + wn * 64 + j * 8 + tg * 2;
        *(float2*)&out[(size_t)row0 * DMODEL + n] = make_float2(acc[j].x, acc[j].y);
        *(float2*)&out[(size_t)(row0 + 8) * DMODEL + n] = make_float2(acc[j].z, acc[j].w);
    }
}

// ---------------- launch ----------------
extern "C" void kernel_launch(void* const* d_in, const int* in_sizes, int n_in,
                              void* d_out, int out_size)
{
    const float* resid = (const float*)d_in[0];
    const float* Wq    = (const float*)d_in[1];
    const float* Wk    = (const float*)d_in[2];
    const float* Wv    = (const float*)d_in[3];
    const float* Wo    = (const float*)d_in[4];
    const float* bq    = (const float*)d_in[5];
    const float* bk    = (const float*)d_in[6];
    const float* bv    = (const float*)d_in[7];
    const float* vk    = (const float*)d_in[8];
    const float* vv    = (const float*)d_in[9];
    float* out = (float*)d_out;

    const int ATTN_SMEM = (2 * 1280 + 2 * 2304) * 4;   // 28672
    const int QKV_SMEM  = 128 * 132 * 4;               // 67584 (epilogue stage > pipeline)
    const int OUT_SMEM  = (2 * 64 * 20 + 2 * 128 * 20) * 4;  // 30720
    static int smem_set = 0;
    if (!smem_set) {
        cudaFuncSetAttribute(attn_mma_kernel,
                             cudaFuncAttributeMaxDynamicSharedMemorySize, ATTN_SMEM);
        cudaFuncSetAttribute(qkv_gemm_kernel,
                             cudaFuncAttributeMaxDynamicSharedMemorySize, QKV_SMEM);
        cudaFuncSetAttribute(out_gemm_kernel,
                             cudaFuncAttributeMaxDynamicSharedMemorySize, OUT_SMEM);
        smem_set = 1;
    }

    setup_kernel<<<1024, 256>>>(vk, vv);
    convert_kernel<<<1024, 256>>>(resid, Wv);
    transpose_qk_kernel<<<dim3(32, 32, 2), dim3(32, 32)>>>(Wq, Wk);
    transpose_wo_kernel<<<dim3(64, 32), dim3(32, 32)>>>(Wo);
    qkv_gemm_kernel<<<dim3(32, 16), 256, QKV_SMEM>>>(bq, bk, bv);
    attn_mma_kernel<<<dim3(8, 32, 2), 256, ATTN_SMEM>>>();
    out_gemm_kernel<<<dim3(8, 32), 256, OUT_SMEM>>>(out);
}

// round 12
// speedup vs baseline: 1.1043x; 1.1043x over previous
#include <cuda_runtime.h>
#include <cuda_fp16.h>
#include <math.h>
#include <stdint.h>

#define SEQ    1024
#define DMODEL 1024
#define NQK    32
#define DQK    32
#define NOV    2048
#define BATCH  2
#define VKV    16
#define KVLEN  (SEQ + VKV)   /* 1040 */
#define KVPAD  1088          /* padded kv pitch for g_vh */
#define RATIO  (NOV / NQK)   /* 64 */
#define FULLM  0xFFFFFFFFu

// ---------------- scratch (static device globals; no allocation) ----------------
__device__ __half g_qh[(size_t)BATCH * NQK * SEQ   * DQK];   // [b][h][s][d], pre-scaled 1/sqrt(32)
__device__ __half g_kh[(size_t)BATCH * NQK * KVLEN * DQK];   // [b][h][kv][d]
__device__ __half g_vh[(size_t)BATCH * NOV * KVPAD];         // [b][n][kv]  (transposed, padded)
__device__ __half g_zh[(size_t)BATCH * SEQ * NOV];           // [bs][n]
__device__ __half g_xh[(size_t)BATCH * SEQ * DMODEL];        // resid as half [m][k]
__device__ __half g_bh[(size_t)4096 * DMODEL];               // [Wq^T | Wk^T | Wv] as [n][k]
__device__ __half g_woh[(size_t)DMODEL * NOV];               // Wo^T as [n][k]
__device__ float  g_sin[SEQ * 16];
__device__ float  g_cos[SEQ * 16];

// ---------------- helpers ----------------
__device__ __forceinline__ uint32_t packh2(float lo, float hi) {
    __half2 h = __floats2half2_rn(lo, hi);
    return *(uint32_t*)&h;
}
__device__ __forceinline__ void mma16(float4& d, const uint32_t* a, const uint32_t* b) {
    asm volatile(
        "mma.sync.aligned.m16n8k16.row.col.f32.f16.f16.f32 "
        "{%0,%1,%2,%3}, {%4,%5,%6,%7}, {%8,%9}, {%0,%1,%2,%3};\n"
        : "+f"(d.x), "+f"(d.y), "+f"(d.z), "+f"(d.w)
        : "r"(a[0]), "r"(a[1]), "r"(a[2]), "r"(a[3]), "r"(b[0]), "r"(b[1]));
}
__device__ __forceinline__ void cp_async16(uint32_t dst_smem, const void* src, int src_bytes) {
    asm volatile("cp.async.cg.shared.global [%0], [%1], 16, %2;"
                 :: "r"(dst_smem), "l"(src), "r"(src_bytes));
}
__device__ __forceinline__ void ldsm4(uint32_t& r0, uint32_t& r1, uint32_t& r2, uint32_t& r3,
                                      uint32_t addr) {
    asm volatile("ldmatrix.sync.aligned.m8n8.x4.shared.b16 {%0,%1,%2,%3}, [%4];"
                 : "=r"(r0), "=r"(r1), "=r"(r2), "=r"(r3) : "r"(addr));
}

// ---------------- prep: rotary table + virtual k/v + V pad + resid/Wv converts ------
__global__ void __launch_bounds__(256) prep_kernel(
    const float* __restrict__ resid, const float* __restrict__ Wv,
    const float* __restrict__ vk, const float* __restrict__ vv)
{
    int i = blockIdx.x * blockDim.x + threadIdx.x;   // 262144 threads
    // converts: 8 elems each over 2M
    size_t base = (size_t)i * 8;
    float4 a0 = *(const float4*)(resid + base);
    float4 a1 = *(const float4*)(resid + base + 4);
    *(uint4*)&g_xh[base] = make_uint4(packh2(a0.x, a0.y), packh2(a0.z, a0.w),
                                      packh2(a1.x, a1.y), packh2(a1.z, a1.w));
    float4 b0 = *(const float4*)(Wv + base);
    float4 b1 = *(const float4*)(Wv + base + 4);
    *(uint4*)&g_bh[(size_t)2048 * DMODEL + base] =
        make_uint4(packh2(b0.x, b0.y), packh2(b0.z, b0.w),
                   packh2(b1.x, b1.y), packh2(b1.z, b1.w));
    // rotary table
    if (i < SEQ * 16) {
        int pos = i >> 4, jm = i & 15;
        float freq = powf(10000.0f, (float)jm * (1.0f / 16.0f));
        float ang = (float)pos / freq;
        g_sin[i] = sinf(ang);
        g_cos[i] = cosf(ang);
    }
    // virtual k
    if (i < BATCH * NQK * VKV * DQK) {
        int d  = i & 31;
        int tt = (i >> 5) & 15;
        int h  = (i >> 9) & 31;
        int b  = i >> 14;
        g_kh[(((size_t)b * NQK + h) * KVLEN + SEQ + tt) * DQK + d] =
            __float2half(vk[((size_t)tt * NQK + h) * DQK + d]);
    }
    // virtual v + zero pad (g_vh cols 1024..1087)
    if (i < BATCH * NOV * 64) {
        int c = 1024 + (i & 63);
        int n = (i >> 6) & 2047;
        int b = i >> 17;
        float val = (c < KVLEN) ? vv[(size_t)(c - SEQ) * NOV + n] : 0.f;
        g_vh[((size_t)b * NOV + n) * KVPAD + c] = __float2half(val);
    }
}

// ---------------- tiled transpose: Wq/Wk [h][m][d] -> g_bh [h*32+d][m] ----------------
__global__ void transpose_qk_kernel(const float* __restrict__ Wq,
                                    const float* __restrict__ Wk)
{
    __shared__ float sm[32][33];
    int m0 = blockIdx.x * 32;
    int h  = blockIdx.y;
    int z  = blockIdx.z;
    const float* W = z ? Wk : Wq;
    int tx = threadIdx.x, ty = threadIdx.y;
    sm[ty][tx] = W[((size_t)h * 1024 + m0 + ty) * 32 + tx];
    __syncthreads();
    g_bh[((size_t)z * 1024 + h * 32 + ty) * DMODEL + m0 + tx] = __float2half(sm[tx][ty]);
}

// ---------------- tiled transpose: Wo [k][n] -> g_woh [n][k] ----------------
__global__ void transpose_wo_kernel(const float* __restrict__ Wo)
{
    __shared__ float sm[32][33];
    int k0 = blockIdx.x * 32;
    int n0 = blockIdx.y * 32;
    int tx = threadIdx.x, ty = threadIdx.y;
    sm[ty][tx] = Wo[(size_t)(k0 + ty) * DMODEL + n0 + tx];
    __syncthreads();
    g_woh[(size_t)(n0 + ty) * NOV + k0 + tx] = __float2half(sm[tx][ty]);
}

// ---------------- fused QKV GEMM: fp16 mma, 3-stage cp.async, ldmatrix frags ---------
// C[2048 x 4096] = g_xh @ g_bh^T. BM=128, BN=128, BK=32. Stage = A[128*20]+B[128*20] words.
__global__ void __launch_bounds__(256, 2) qkv_gemm_kernel(
    const float* __restrict__ bq, const float* __restrict__ bk,
    const float* __restrict__ bv)
{
    extern __shared__ uint32_t dsm[];            // 3*5120 words pipeline; epilogue 16896 words
    float (*Cs)[132] = (float(*)[132])dsm;       // f32 stage alias (Q/K epilogue)
    __half* Ch = (__half*)dsm;                   // half stage alias (V epilogue)
    uint32_t smb = (uint32_t)__cvta_generic_to_shared(dsm);

    int nt = blockIdx.x;
    int n0 = nt * 128;
    int r0 = blockIdx.y * 128;
    int region = (nt < 8) ? 0 : (nt < 16) ? 1 : 2;
    int cb = (region == 0) ? n0 : (region == 1) ? n0 - 1024 : n0 - 2048;
    int hbase = cb >> 5;

    int t = threadIdx.x, w = t >> 5, lane = t & 31;
    int g = lane >> 2, tg = lane & 3;
    int wm = w >> 1, wn = w & 1;

    float4 acc[2][8];
    #pragma unroll
    for (int i = 0; i < 2; i++)
        #pragma unroll
        for (int j = 0; j < 8; j++) acc[i][j] = make_float4(0.f, 0.f, 0.f, 0.f);

    const __half* Abase = g_xh + (size_t)r0 * DMODEL;
    const __half* Bbase = g_bh + (size_t)n0 * DMODEL;

    // ldmatrix lane address components (word offsets within a stage)
    int a_row = (lane & 15);                       // + rm
    int a_koff = (lane & 16) ? 4 : 0;              // +4 words = +8 halfs for k-high
    int b_row = (lane & 7) + ((lane & 16) ? 8 : 0);
    int b_koff = (lane & 8) ? 4 : 0;

    auto issue = [&](int kt) {
        int s = ((kt % 3) * 5120);
        int k0 = kt * 32;
        #pragma unroll
        for (int i = 0; i < 2; i++) {
            int idx = t + i * 256;
            int row = idx >> 2, seg = idx & 3;
            cp_async16(smb + (s + row * 20 + seg * 4) * 4,
                       Abase + (size_t)row * DMODEL + k0 + seg * 8, 16);
            cp_async16(smb + (s + 2560 + row * 20 + seg * 4) * 4,
                       Bbase + (size_t)row * DMODEL + k0 + seg * 8, 16);
        }
        asm volatile("cp.async.commit_group;" ::: "memory");
    };

    issue(0); issue(1);
    for (int kt = 0; kt < 32; kt++) {
        if (kt < 31) asm volatile("cp.async.wait_group 1;" ::: "memory");
        else         asm volatile("cp.async.wait_group 0;" ::: "memory");
        __syncthreads();
        if (kt + 2 < 32) issue(kt + 2);

        uint32_t sA = smb + ((kt % 3) * 5120) * 4;
        uint32_t sB = sA + 2560 * 4;
        #pragma unroll
        for (int kb = 0; kb < 2; kb++) {
            uint32_t af[2][4];
            #pragma unroll
            for (int i = 0; i < 2; i++) {
                int rm = wm * 32 + i * 16;
                ldsm4(af[i][0], af[i][1], af[i][2], af[i][3],
                      sA + ((rm + a_row) * 20 + kb * 8 + a_koff) * 4);
            }
            #pragma unroll
            for (int p = 0; p < 4; p++) {
                int nb = wn * 64 + p * 16;
                uint32_t bf0, bf1, bf2, bf3;
                ldsm4(bf0, bf1, bf2, bf3,
                      sB + ((nb + b_row) * 20 + kb * 8 + b_koff) * 4);
                uint32_t b01[2] = { bf0, bf1 };
                uint32_t b23[2] = { bf2, bf3 };
                mma16(acc[0][2 * p],     af[0], b01);
                mma16(acc[1][2 * p],     af[1], b01);
                mma16(acc[0][2 * p + 1], af[0], b23);
                mma16(acc[1][2 * p + 1], af[1], b23);
            }
        }
    }
    __syncthreads();   // pipeline smem reads done before epilogue staging overwrites it

    if (region == 2) {
        // ---- V epilogue: bias + transpose-stage in smem, coalesced half STG ----
        int nv0 = cb;
        #pragma unroll
        for (int i = 0; i < 2; i++) {
            int rl = wm * 32 + i * 16 + g;
            #pragma unroll
            for (int j = 0; j < 8; j++) {
                int n = wn * 64 + j * 8 + tg * 2;
                float2 bvv = *(const float2*)(bv + nv0 + n);
                Ch[(size_t)n       * 136 + rl    ] = __float2half(acc[i][j].x + bvv.x);
                Ch[(size_t)(n + 1) * 136 + rl    ] = __float2half(acc[i][j].y + bvv.y);
                Ch[(size_t)n       * 136 + rl + 8] = __float2half(acc[i][j].z + bvv.x);
                Ch[(size_t)(n + 1) * 136 + rl + 8] = __float2half(acc[i][j].w + bvv.y);
            }
        }
        __syncthreads();
        int b = r0 >> 10, s0 = r0 & 1023;
        #pragma unroll
        for (int p = 0; p < 8; p++) {
            int idx = t + p * 256;
            int n = idx >> 4, c8 = (idx & 15) * 8;
            uint4 v = *(uint4*)&Ch[(size_t)n * 136 + c8];
            *(uint4*)&g_vh[((size_t)b * NOV + nv0 + n) * KVPAD + s0 + c8] = v;
        }
    } else {
        // ---- Q/K epilogue: bias stage + rotary scatter ----
        const float* bias = (region == 0) ? bq : bk;
        #pragma unroll
        for (int i = 0; i < 2; i++) {
            int rr = wm * 32 + i * 16 + g;
            #pragma unroll
            for (int j = 0; j < 8; j++) {
                int c = wn * 64 + j * 8 + tg * 2;
                float b0 = bias[cb + c];
                float b1 = bias[cb + c + 1];
                Cs[rr    ][c    ] = acc[i][j].x + b0;
                Cs[rr    ][c + 1] = acc[i][j].y + b1;
                Cs[rr + 8][c    ] = acc[i][j].z + b0;
                Cs[rr + 8][c + 1] = acc[i][j].w + b1;
            }
        }
        __syncthreads();

        const float invscale = 0.17677669529663687f;   // 1/sqrt(32)
        float sc = (region == 0) ? invscale : 1.f;
        #pragma unroll
        for (int p = 0; p < 2; p++) {
            int idx = t + p * 256;
            int r = idx >> 2, hh = idx & 3;
            int grow = r0 + r;
            int bb = grow >> 10, pos = grow & 1023;
            int h = hbase + hh;
            const float* base = &Cs[r][hh * 32];
            __half* dst = (region == 0)
                ? g_qh + (((size_t)bb * NQK + h) * SEQ   + pos) * DQK
                : g_kh + (((size_t)bb * NQK + h) * KVLEN + pos) * DQK;
            #pragma unroll
            for (int c = 0; c < 32; c++) {
                float val  = base[c];
                float flip = (c < 16) ? -base[c + 16] : base[c - 16];
                int jm = c & 15;
                float sn = g_sin[pos * 16 + jm];
                float cs = g_cos[pos * 16 + jm];
                dst[c] = __float2half((val * cs + flip * sn) * sc);
            }
        }
    }
}

// ---------------- attention: fp16 mma flash, cp.async double-buffered (unchanged) ----
__global__ void __launch_bounds__(256, 2) attn_mma_kernel()
{
    extern __shared__ uint32_t smem[];
    uint32_t* Kb0 = smem;                  // per buffer 64*20 = 1280 words
    uint32_t* Vb0 = smem + 2 * 1280;       // per buffer 64*36 = 2304 words

    int qt = 7 - blockIdx.x;
    int h = blockIdx.y, b = blockIdx.z;
    int i0 = qt * 128;
    int t = threadIdx.x, w = t >> 5, lane = t & 31;
    int g = lane >> 2, tg = lane & 3;

    const __half* kbp = g_kh + ((size_t)b * NQK + h) * KVLEN * DQK;
    const __half* vbp = g_vh + ((size_t)b * NOV + h * RATIO) * KVPAD;

    uint32_t qf[2][4];
    {
        const __half* qb = g_qh + (((size_t)b * NQK + h) * SEQ + i0 + w * 16) * DQK;
        #pragma unroll
        for (int kb = 0; kb < 2; kb++) {
            qf[kb][0] = *(const uint32_t*)(qb + (size_t)g       * DQK + kb * 16 + 2 * tg);
            qf[kb][1] = *(const uint32_t*)(qb + (size_t)(g + 8) * DQK + kb * 16 + 2 * tg);
            qf[kb][2] = *(const uint32_t*)(qb + (size_t)g       * DQK + kb * 16 + 8 + 2 * tg);
            qf[kb][3] = *(const uint32_t*)(qb + (size_t)(g + 8) * DQK + kb * 16 + 8 + 2 * tg);
        }
    }

    float m_lo = -INFINITY, m_hi = -INFINITY, l_lo = 0.f, l_hi = 0.f;
    float4 z[8];
    #pragma unroll
    for (int j = 0; j < 8; j++) z[j] = make_float4(0.f, 0.f, 0.f, 0.f);

    int row_lo = i0 + w * 16 + g;
    int row_hi = row_lo + 8;
    int warp_min_row = i0 + w * 16;

    int jlim = i0 + 128 + VKV;
    if (jlim > KVLEN) jlim = KVLEN;
    int nch = (jlim + 63) >> 6;

    auto issue = [&](int ch) {
        int kv0 = ch << 6;
        uint32_t* K = Kb0 + (ch & 1) * 1280;
        uint32_t* V = Vb0 + (ch & 1) * 2304;
        {
            int row = t >> 2, seg = t & 3;
            int gj = kv0 + row;
            int cg2 = gj < KVLEN ? gj : KVLEN - 1;
            uint32_t dst = (uint32_t)__cvta_generic_to_shared(&K[row * 20 + seg * 4]);
            cp_async16(dst, kbp + (size_t)cg2 * DQK + seg * 8, gj < KVLEN ? 16 : 0);
        }
        #pragma unroll
        for (int i = 0; i < 2; i++) {
            int idx = t + i * 256;
            int row = idx >> 3, seg = idx & 7;
            uint32_t dst = (uint32_t)__cvta_generic_to_shared(&V[row * 36 + seg * 4]);
            cp_async16(dst, vbp + (size_t)row * KVPAD + kv0 + seg * 8, 16);
        }
        asm volatile("cp.async.commit_group;" ::: "memory");
    };

    issue(0);

    for (int ch = 0; ch < nch; ch++) {
        int kv0 = ch << 6;
        if (ch + 1 < nch) {
            issue(ch + 1);
            asm volatile("cp.async.wait_group 1;" ::: "memory");
        } else {
            asm volatile("cp.async.wait_group 0;" ::: "memory");
        }
        __syncthreads();

        uint32_t* K = Kb0 + (ch & 1) * 1280;
        uint32_t* V = Vb0 + (ch & 1) * 2304;

        float4 s[8];
        #pragma unroll
        for (int j = 0; j < 8; j++) s[j] = make_float4(0.f, 0.f, 0.f, 0.f);
        #pragma unroll
        for (int kb = 0; kb < 2; kb++) {
            #pragma unroll
            for (int j = 0; j < 8; j++) {
                int cn = j * 8 + g;
                uint32_t bf[2] = { K[cn * 20 + 8 * kb + tg], K[cn * 20 + 8 * kb + 4 + tg] };
                mma16(s[j], qf[kb], bf);
            }
        }

        if (kv0 + 63 > warp_min_row + VKV || kv0 + 63 >= KVLEN) {
            #pragma unroll
            for (int j = 0; j < 8; j++) {
                int c0 = kv0 + j * 8 + 2 * tg;
                int c1 = c0 + 1;
                s[j].x = (c0 <= row_lo + VKV && c0 < KVLEN) ? s[j].x : -INFINITY;
                s[j].y = (c1 <= row_lo + VKV && c1 < KVLEN) ? s[j].y : -INFINITY;
                s[j].z = (c0 <= row_hi + VKV && c0 < KVLEN) ? s[j].z : -INFINITY;
                s[j].w = (c1 <= row_hi + VKV && c1 < KVLEN) ? s[j].w : -INFINITY;
            }
        }

        float mx_lo = -INFINITY, mx_hi = -INFINITY;
        #pragma unroll
        for (int j = 0; j < 8; j++) {
            mx_lo = fmaxf(mx_lo, fmaxf(s[j].x, s[j].y));
            mx_hi = fmaxf(mx_hi, fmaxf(s[j].z, s[j].w));
        }
        mx_lo = fmaxf(mx_lo, __shfl_xor_sync(FULLM, mx_lo, 1));
        mx_lo = fmaxf(mx_lo, __shfl_xor_sync(FULLM, mx_lo, 2));
        mx_hi = fmaxf(mx_hi, __shfl_xor_sync(FULLM, mx_hi, 1));
        mx_hi = fmaxf(mx_hi, __shfl_xor_sync(FULLM, mx_hi, 2));
        float mn_lo = fmaxf(m_lo, mx_lo);
        float mn_hi = fmaxf(m_hi, mx_hi);
        float corr_lo = __expf(m_lo - mn_lo);
        float corr_hi = __expf(m_hi - mn_hi);

        float ps_lo = 0.f, ps_hi = 0.f;
        #pragma unroll
        for (int j = 0; j < 8; j++) {
            s[j].x = __expf(s[j].x - mn_lo);
            s[j].y = __expf(s[j].y - mn_lo);
            s[j].z = __expf(s[j].z - mn_hi);
            s[j].w = __expf(s[j].w - mn_hi);
            ps_lo += s[j].x + s[j].y;
            ps_hi += s[j].z + s[j].w;
        }
        ps_lo += __shfl_xor_sync(FULLM, ps_lo, 1);
        ps_lo += __shfl_xor_sync(FULLM, ps_lo, 2);
        ps_hi += __shfl_xor_sync(FULLM, ps_hi, 1);
        ps_hi += __shfl_xor_sync(FULLM, ps_hi, 2);
        l_lo = l_lo * corr_lo + ps_lo;
        l_hi = l_hi * corr_hi + ps_hi;
        m_lo = mn_lo; m_hi = mn_hi;
        #pragma unroll
        for (int j = 0; j < 8; j++) {
            z[j].x *= corr_lo; z[j].y *= corr_lo;
            z[j].z *= corr_hi; z[j].w *= corr_hi;
        }

        #pragma unroll
        for (int kb = 0; kb < 4; kb++) {
            uint32_t af[4];
            af[0] = packh2(s[2 * kb].x,     s[2 * kb].y);
            af[1] = packh2(s[2 * kb].z,     s[2 * kb].w);
            af[2] = packh2(s[2 * kb + 1].x, s[2 * kb + 1].y);
            af[3] = packh2(s[2 * kb + 1].z, s[2 * kb + 1].w);
            #pragma unroll
            for (int j = 0; j < 8; j++) {
                int cn = j * 8 + g;
                uint32_t bf[2] = { V[cn * 36 + 8 * kb + tg], V[cn * 36 + 8 * kb + 4 + tg] };
                mma16(z[j], af, bf);
            }
        }
        __syncthreads();
    }

    float li_lo = 1.f / l_lo;
    float li_hi = 1.f / l_hi;
    __half* zlo = g_zh + ((size_t)b * SEQ + row_lo) * NOV + h * RATIO;
    __half* zhi = g_zh + ((size_t)b * SEQ + row_hi) * NOV + h * RATIO;
    #pragma unroll
    for (int j = 0; j < 8; j++) {
        int col = j * 8 + 2 * tg;
        *(uint32_t*)&zlo[col] = packh2(z[j].x * li_lo, z[j].y * li_lo);
        *(uint32_t*)&zhi[col] = packh2(z[j].z * li_hi, z[j].w * li_hi);
    }
}

// ---------------- output GEMM: fp16 mma, 3-stage cp.async, ldmatrix. BM=64, BN=128 ----
// Stage = A[64*20] + B[128*20] = 3840 words.
__global__ void __launch_bounds__(256, 2) out_gemm_kernel(float* __restrict__ out)
{
    extern __shared__ uint32_t dsm[];
    uint32_t smb = (uint32_t)__cvta_generic_to_shared(dsm);

    int n0 = blockIdx.x * 128, r0 = blockIdx.y * 64;
    int t = threadIdx.x;
    int w = t >> 5, lane = t & 31;
    int g = lane >> 2, tg = lane & 3;
    int wm = w >> 1, wn = w & 1;

    float4 acc[8];
    #pragma unroll
    for (int j = 0; j < 8; j++) acc[j] = make_float4(0.f, 0.f, 0.f, 0.f);

    const __half* Abase = g_zh + (size_t)r0 * NOV;
    const __half* Bbase = g_woh + (size_t)n0 * NOV;

    int a_row = (lane & 15);
    int a_koff = (lane & 16) ? 4 : 0;
    int b_row = (lane & 7) + ((lane & 16) ? 8 : 0);
    int b_koff = (lane & 8) ? 4 : 0;

    auto issue = [&](int kt) {
        int s = (kt % 3) * 3840;
        int k0 = kt * 32;
        {
            int row = t >> 2, seg = t & 3;
            cp_async16(smb + (s + row * 20 + seg * 4) * 4,
                       Abase + (size_t)row * NOV + k0 + seg * 8, 16);
        }
        #pragma unroll
        for (int i = 0; i < 2; i++) {
            int idx = t + i * 256;
            int row = idx >> 2, seg = idx & 3;
            cp_async16(smb + (s + 1280 + row * 20 + seg * 4) * 4,
                       Bbase + (size_t)row * NOV + k0 + seg * 8, 16);
        }
        asm volatile("cp.async.commit_group;" ::: "memory");
    };

    issue(0); issue(1);
    for (int kt = 0; kt < 64; kt++) {
        if (kt < 63) asm volatile("cp.async.wait_group 1;" ::: "memory");
        else         asm volatile("cp.async.wait_group 0;" ::: "memory");
        __syncthreads();
        if (kt + 2 < 64) issue(kt + 2);

        uint32_t sA = smb + ((kt % 3) * 3840) * 4;
        uint32_t sB = sA + 1280 * 4;
        #pragma unroll
        for (int kb = 0; kb < 2; kb++) {
            uint32_t af[4];
            int rm = wm * 16;
            ldsm4(af[0], af[1], af[2], af[3],
                  sA + ((rm + a_row) * 20 + kb * 8 + a_koff) * 4);
            #pragma unroll
            for (int p = 0; p < 4; p++) {
                int nb = wn * 64 + p * 16;
                uint32_t bf0, bf1, bf2, bf3;
                ldsm4(bf0, bf1, bf2, bf3,
                      sB + ((nb + b_row) * 20 + kb * 8 + b_koff) * 4);
                uint32_t b01[2] = { bf0, bf1 };
                uint32_t b23[2] = { bf2, bf3 };
                mma16(acc[2 * p],     af, b01);
                mma16(acc[2 * p + 1], af, b23);
            }
        }
    }

    int row0 = r0 + wm * 16 + g;
    #pragma unroll
    for (int j = 0; j < 8; j++) {
        int n = n0 + wn * 64 + j * 8 + tg * 2;
        *(float2*)&out[(size_t)row0 * DMODEL + n] = make_float2(acc[j].x, acc[j].y);
        *(float2*)&out[(size_t)(row0 + 8) * DMODEL + n] = make_float2(acc[j].z, acc[j].w);
    }
}

// ---------------- launch ----------------
extern "C" void kernel_launch(void* const* d_in, const int* in_sizes, int n_in,
                              void* d_out, int out_size)
{
    const float* resid = (const float*)d_in[0];
    const float* Wq    = (const float*)d_in[1];
    const float* Wk    = (const float*)d_in[2];
    const float* Wv    = (const float*)d_in[3];
    const float* Wo    = (const float*)d_in[4];
    const float* bq    = (const float*)d_in[5];
    const float* bk    = (const float*)d_in[6];
    const float* bv    = (const float*)d_in[7];
    const float* vk    = (const float*)d_in[8];
    const float* vv    = (const float*)d_in[9];
    float* out = (float*)d_out;

    const int ATTN_SMEM = (2 * 1280 + 2 * 2304) * 4;   // 28672
    const int QKV_SMEM  = 128 * 132 * 4;               // 67584 (epilogue stage > 3*5120*4)
    const int OUT_SMEM  = 3 * 3840 * 4;                // 46080
    static int smem_set = 0;
    if (!smem_set) {
        cudaFuncSetAttribute(attn_mma_kernel,
                             cudaFuncAttributeMaxDynamicSharedMemorySize, ATTN_SMEM);
        cudaFuncSetAttribute(qkv_gemm_kernel,
                             cudaFuncAttributeMaxDynamicSharedMemorySize, QKV_SMEM);
        cudaFuncSetAttribute(out_gemm_kernel,
                             cudaFuncAttributeMaxDynamicSharedMemorySize, OUT_SMEM);
        smem_set = 1;
    }

    prep_kernel<<<1024, 256>>>(resid, Wv, vk, vv);
    transpose_qk_kernel<<<dim3(32, 32, 2), dim3(32, 32)>>>(Wq, Wk);
    transpose_wo_kernel<<<dim3(64, 32), dim3(32, 32)>>>(Wo);
    qkv_gemm_kernel<<<dim3(32, 16), 256, QKV_SMEM>>>(bq, bk, bv);
    attn_mma_kernel<<<dim3(8, 32, 2), 256, ATTN_SMEM>>>();
    out_gemm_kernel<<<dim3(8, 32), 256, OUT_SMEM>>>(out);
}

// round 13
// speedup vs baseline: 1.2336x; 1.1171x over previous
#include <cuda_runtime.h>
#include <cuda_fp16.h>
#include <math.h>
#include <stdint.h>

#define SEQ    1024
#define DMODEL 1024
#define NQK    32
#define DQK    32
#define NOV    2048
#define BATCH  2
#define VKV    16
#define KVLEN  (SEQ + VKV)   /* 1040 */
#define KVPAD  1088          /* padded kv pitch for g_vh */
#define RATIO  (NOV / NQK)   /* 64 */
#define FULLM  0xFFFFFFFFu

// ---------------- scratch (static device globals; no allocation) ----------------
__device__ __half g_qh[(size_t)BATCH * NQK * SEQ   * DQK];   // [b][h][s][d], pre-scaled 1/sqrt(32)
__device__ __half g_kh[(size_t)BATCH * NQK * KVLEN * DQK];   // [b][h][kv][d]
__device__ __half g_vh[(size_t)BATCH * NOV * KVPAD];         // [b][n][kv]  (transposed, padded)
__device__ __half g_zh[(size_t)BATCH * SEQ * NOV];           // [bs][n]
__device__ __half g_xh[(size_t)BATCH * SEQ * DMODEL];        // resid as half [m][k]
__device__ __half g_bh[(size_t)4096 * DMODEL];               // [Wq^T | Wk^T | Wv] as [n][k]
__device__ __half g_woh[(size_t)DMODEL * NOV];               // Wo^T as [n][k]
__device__ float  g_sin[SEQ * 16];
__device__ float  g_cos[SEQ * 16];

// ---------------- helpers ----------------
__device__ __forceinline__ uint32_t packh2(float lo, float hi) {
    __half2 h = __floats2half2_rn(lo, hi);
    return *(uint32_t*)&h;
}
__device__ __forceinline__ void mma16(float4& d, const uint32_t* a, const uint32_t* b) {
    asm volatile(
        "mma.sync.aligned.m16n8k16.row.col.f32.f16.f16.f32 "
        "{%0,%1,%2,%3}, {%4,%5,%6,%7}, {%8,%9}, {%0,%1,%2,%3};\n"
        : "+f"(d.x), "+f"(d.y), "+f"(d.z), "+f"(d.w)
        : "r"(a[0]), "r"(a[1]), "r"(a[2]), "r"(a[3]), "r"(b[0]), "r"(b[1]));
}
__device__ __forceinline__ void cp_async16(uint32_t dst_smem, const void* src, int src_bytes) {
    asm volatile("cp.async.cg.shared.global [%0], [%1], 16, %2;"
                 :: "r"(dst_smem), "l"(src), "r"(src_bytes));
}
__device__ __forceinline__ void ldsm4(uint32_t& r0, uint32_t& r1, uint32_t& r2, uint32_t& r3,
                                      uint32_t addr) {
    asm volatile("ldmatrix.sync.aligned.m8n8.x4.shared.b16 {%0,%1,%2,%3}, [%4];"
                 : "=r"(r0), "=r"(r1), "=r"(r2), "=r"(r3) : "r"(addr));
}

// ---------------- prep: rotary table + virtual k/v + V pad + resid/Wv converts ------
__global__ void __launch_bounds__(256) prep_kernel(
    const float* __restrict__ resid, const float* __restrict__ Wv,
    const float* __restrict__ vk, const float* __restrict__ vv)
{
    int i = blockIdx.x * blockDim.x + threadIdx.x;   // 262144 threads
    size_t base = (size_t)i * 8;
    float4 a0 = *(const float4*)(resid + base);
    float4 a1 = *(const float4*)(resid + base + 4);
    *(uint4*)&g_xh[base] = make_uint4(packh2(a0.x, a0.y), packh2(a0.z, a0.w),
                                      packh2(a1.x, a1.y), packh2(a1.z, a1.w));
    float4 b0 = *(const float4*)(Wv + base);
    float4 b1 = *(const float4*)(Wv + base + 4);
    *(uint4*)&g_bh[(size_t)2048 * DMODEL + base] =
        make_uint4(packh2(b0.x, b0.y), packh2(b0.z, b0.w),
                   packh2(b1.x, b1.y), packh2(b1.z, b1.w));
    if (i < SEQ * 16) {
        int pos = i >> 4, jm = i & 15;
        float freq = powf(10000.0f, (float)jm * (1.0f / 16.0f));
        float ang = (float)pos / freq;
        g_sin[i] = sinf(ang);
        g_cos[i] = cosf(ang);
    }
    if (i < BATCH * NQK * VKV * DQK) {
        int d  = i & 31;
        int tt = (i >> 5) & 15;
        int h  = (i >> 9) & 31;
        int b  = i >> 14;
        g_kh[(((size_t)b * NQK + h) * KVLEN + SEQ + tt) * DQK + d] =
            __float2half(vk[((size_t)tt * NQK + h) * DQK + d]);
    }
    if (i < BATCH * NOV * 64) {
        int c = 1024 + (i & 63);
        int n = (i >> 6) & 2047;
        int b = i >> 17;
        float val = (c < KVLEN) ? vv[(size_t)(c - SEQ) * NOV + n] : 0.f;
        g_vh[((size_t)b * NOV + n) * KVPAD + c] = __float2half(val);
    }
}

// ---------------- tiled transpose: Wq/Wk [h][m][d] -> g_bh [h*32+d][m] ----------------
__global__ void transpose_qk_kernel(const float* __restrict__ Wq,
                                    const float* __restrict__ Wk)
{
    __shared__ float sm[32][33];
    int m0 = blockIdx.x * 32;
    int h  = blockIdx.y;
    int z  = blockIdx.z;
    const float* W = z ? Wk : Wq;
    int tx = threadIdx.x, ty = threadIdx.y;
    sm[ty][tx] = W[((size_t)h * 1024 + m0 + ty) * 32 + tx];
    __syncthreads();
    g_bh[((size_t)z * 1024 + h * 32 + ty) * DMODEL + m0 + tx] = __float2half(sm[tx][ty]);
}

// ---------------- tiled transpose: Wo [k][n] -> g_woh [n][k] ----------------
__global__ void transpose_wo_kernel(const float* __restrict__ Wo)
{
    __shared__ float sm[32][33];
    int k0 = blockIdx.x * 32;
    int n0 = blockIdx.y * 32;
    int tx = threadIdx.x, ty = threadIdx.y;
    sm[ty][tx] = Wo[(size_t)(k0 + ty) * DMODEL + n0 + tx];
    __syncthreads();
    g_woh[(size_t)(n0 + ty) * NOV + k0 + tx] = __float2half(sm[tx][ty]);
}

// ---------------- fused QKV GEMM: fp16 mma, BK=64 XOR-swizzled, 3-stage cp.async ------
// C[2048 x 4096] = g_xh @ g_bh^T. BM=128, BN=128, BK=64, 16 k-iters.
// Stage: A[128 rows x 32 words] + B[same] = 8192 words (32 KB). Swizzle: 16B-chunk
// c of row r stored at word r*32 + ((c ^ (r&7))<<2). Conflict-free for cp.async AND ldmatrix.
__global__ void __launch_bounds__(256, 2) qkv_gemm_kernel(
    const float* __restrict__ bq, const float* __restrict__ bk,
    const float* __restrict__ bv)
{
    extern __shared__ uint32_t dsm[];            // 3*8192 words pipeline; epilogue 16896 words
    float (*Cs)[132] = (float(*)[132])dsm;       // f32 stage alias (Q/K epilogue)
    __half* Ch = (__half*)dsm;                   // half stage alias (V epilogue)
    uint32_t smb = (uint32_t)__cvta_generic_to_shared(dsm);

    int nt = blockIdx.x;
    int n0 = nt * 128;
    int r0 = blockIdx.y * 128;
    int region = (nt < 8) ? 0 : (nt < 16) ? 1 : 2;
    int cb = (region == 0) ? n0 : (region == 1) ? n0 - 1024 : n0 - 2048;
    int hbase = cb >> 5;

    int t = threadIdx.x, w = t >> 5, lane = t & 31;
    int g = lane >> 2, tg = lane & 3;
    int wm = w >> 1, wn = w & 1;

    float4 acc[2][8];
    #pragma unroll
    for (int i = 0; i < 2; i++)
        #pragma unroll
        for (int j = 0; j < 8; j++) acc[i][j] = make_float4(0.f, 0.f, 0.f, 0.f);

    const __half* Abase = g_xh + (size_t)r0 * DMODEL;
    const __half* Bbase = g_bh + (size_t)n0 * DMODEL;

    // per-lane fragment address components
    int a_r = lane & 15;                 // + rm
    int a_chi = (lane >> 4) & 1;         // k-high chunk
    int b_r = (lane & 7) + ((lane & 16) ? 8 : 0);
    int b_chi = (lane >> 3) & 1;

    auto issue = [&](int kt) {
        int s = (kt % 3) * 8192;
        int k0 = kt * 64;
        #pragma unroll
        for (int i = 0; i < 4; i++) {
            int idx = t + i * 256;                 // 1024 chunks each for A and B
            int row = idx >> 3, c = idx & 7;
            int sw = ((c ^ (row & 7)) << 2);
            cp_async16(smb + (s + row * 32 + sw) * 4,
                       Abase + (size_t)row * DMODEL + k0 + c * 8, 16);
            cp_async16(smb + (s + 4096 + row * 32 + sw) * 4,
                       Bbase + (size_t)row * DMODEL + k0 + c * 8, 16);
        }
        asm volatile("cp.async.commit_group;" ::: "memory");
    };

    issue(0); issue(1);
    for (int kt = 0; kt < 16; kt++) {
        if (kt < 15) asm volatile("cp.async.wait_group 1;" ::: "memory");
        else         asm volatile("cp.async.wait_group 0;" ::: "memory");
        __syncthreads();
        if (kt + 2 < 16) issue(kt + 2);

        uint32_t sA = smb + ((kt % 3) * 8192) * 4;
        uint32_t sB = sA + 4096 * 4;
        #pragma unroll
        for (int kb = 0; kb < 4; kb++) {
            uint32_t af[2][4];
            #pragma unroll
            for (int i = 0; i < 2; i++) {
                int row = wm * 32 + i * 16 + a_r;
                int c = kb * 2 + a_chi;
                ldsm4(af[i][0], af[i][1], af[i][2], af[i][3],
                      sA + (row * 32 + ((c ^ (row & 7)) << 2)) * 4);
            }
            #pragma unroll
            for (int p = 0; p < 4; p++) {
                int row = wn * 64 + p * 16 + b_r;
                int c = kb * 2 + b_chi;
                uint32_t bf0, bf1, bf2, bf3;
                ldsm4(bf0, bf1, bf2, bf3,
                      sB + (row * 32 + ((c ^ (row & 7)) << 2)) * 4);
                uint32_t b01[2] = { bf0, bf1 };
                uint32_t b23[2] = { bf2, bf3 };
                mma16(acc[0][2 * p],     af[0], b01);
                mma16(acc[1][2 * p],     af[1], b01);
                mma16(acc[0][2 * p + 1], af[0], b23);
                mma16(acc[1][2 * p + 1], af[1], b23);
            }
        }
    }
    __syncthreads();   // pipeline reads done before epilogue staging overwrites smem

    if (region == 2) {
        // ---- V epilogue: bias + transpose-stage in smem, coalesced half STG ----
        int nv0 = cb;
        #pragma unroll
        for (int i = 0; i < 2; i++) {
            int rl = wm * 32 + i * 16 + g;
            #pragma unroll
            for (int j = 0; j < 8; j++) {
                int n = wn * 64 + j * 8 + tg * 2;
                float2 bvv = *(const float2*)(bv + nv0 + n);
                Ch[(size_t)n       * 136 + rl    ] = __float2half(acc[i][j].x + bvv.x);
                Ch[(size_t)(n + 1) * 136 + rl    ] = __float2half(acc[i][j].y + bvv.y);
                Ch[(size_t)n       * 136 + rl + 8] = __float2half(acc[i][j].z + bvv.x);
                Ch[(size_t)(n + 1) * 136 + rl + 8] = __float2half(acc[i][j].w + bvv.y);
            }
        }
        __syncthreads();
        int b = r0 >> 10, s0 = r0 & 1023;
        #pragma unroll
        for (int p = 0; p < 8; p++) {
            int idx = t + p * 256;
            int n = idx >> 4, c8 = (idx & 15) * 8;
            uint4 v = *(uint4*)&Ch[(size_t)n * 136 + c8];
            *(uint4*)&g_vh[((size_t)b * NOV + nv0 + n) * KVPAD + s0 + c8] = v;
        }
    } else {
        // ---- Q/K epilogue: bias stage + rotary scatter ----
        const float* bias = (region == 0) ? bq : bk;
        #pragma unroll
        for (int i = 0; i < 2; i++) {
            int rr = wm * 32 + i * 16 + g;
            #pragma unroll
            for (int j = 0; j < 8; j++) {
                int c = wn * 64 + j * 8 + tg * 2;
                float b0 = bias[cb + c];
                float b1 = bias[cb + c + 1];
                Cs[rr    ][c    ] = acc[i][j].x + b0;
                Cs[rr    ][c + 1] = acc[i][j].y + b1;
                Cs[rr + 8][c    ] = acc[i][j].z + b0;
                Cs[rr + 8][c + 1] = acc[i][j].w + b1;
            }
        }
        __syncthreads();

        const float invscale = 0.17677669529663687f;   // 1/sqrt(32)
        float sc = (region == 0) ? invscale : 1.f;
        #pragma unroll
        for (int p = 0; p < 2; p++) {
            int idx = t + p * 256;
            int r = idx >> 2, hh = idx & 3;
            int grow = r0 + r;
            int bb = grow >> 10, pos = grow & 1023;
            int h = hbase + hh;
            const float* base = &Cs[r][hh * 32];
            __half* dst = (region == 0)
                ? g_qh + (((size_t)bb * NQK + h) * SEQ   + pos) * DQK
                : g_kh + (((size_t)bb * NQK + h) * KVLEN + pos) * DQK;
            #pragma unroll
            for (int c = 0; c < 32; c++) {
                float val  = base[c];
                float flip = (c < 16) ? -base[c + 16] : base[c - 16];
                int jm = c & 15;
                float sn = g_sin[pos * 16 + jm];
                float cs = g_cos[pos * 16 + jm];
                dst[c] = __float2half((val * cs + flip * sn) * sc);
            }
        }
    }
}

// ---------------- attention: fp16 mma flash, cp.async double-buffered (unchanged) ----
__global__ void __launch_bounds__(256, 2) attn_mma_kernel()
{
    extern __shared__ uint32_t smem[];
    uint32_t* Kb0 = smem;                  // per buffer 64*20 = 1280 words
    uint32_t* Vb0 = smem + 2 * 1280;       // per buffer 64*36 = 2304 words

    int qt = 7 - blockIdx.x;
    int h = blockIdx.y, b = blockIdx.z;
    int i0 = qt * 128;
    int t = threadIdx.x, w = t >> 5, lane = t & 31;
    int g = lane >> 2, tg = lane & 3;

    const __half* kbp = g_kh + ((size_t)b * NQK + h) * KVLEN * DQK;
    const __half* vbp = g_vh + ((size_t)b * NOV + h * RATIO) * KVPAD;

    uint32_t qf[2][4];
    {
        const __half* qb = g_qh + (((size_t)b * NQK + h) * SEQ + i0 + w * 16) * DQK;
        #pragma unroll
        for (int kb = 0; kb < 2; kb++) {
            qf[kb][0] = *(const uint32_t*)(qb + (size_t)g       * DQK + kb * 16 + 2 * tg);
            qf[kb][1] = *(const uint32_t*)(qb + (size_t)(g + 8) * DQK + kb * 16 + 2 * tg);
            qf[kb][2] = *(const uint32_t*)(qb + (size_t)g       * DQK + kb * 16 + 8 + 2 * tg);
            qf[kb][3] = *(const uint32_t*)(qb + (size_t)(g + 8) * DQK + kb * 16 + 8 + 2 * tg);
        }
    }

    float m_lo = -INFINITY, m_hi = -INFINITY, l_lo = 0.f, l_hi = 0.f;
    float4 z[8];
    #pragma unroll
    for (int j = 0; j < 8; j++) z[j] = make_float4(0.f, 0.f, 0.f, 0.f);

    int row_lo = i0 + w * 16 + g;
    int row_hi = row_lo + 8;
    int warp_min_row = i0 + w * 16;

    int jlim = i0 + 128 + VKV;
    if (jlim > KVLEN) jlim = KVLEN;
    int nch = (jlim + 63) >> 6;

    auto issue = [&](int ch) {
        int kv0 = ch << 6;
        uint32_t* K = Kb0 + (ch & 1) * 1280;
        uint32_t* V = Vb0 + (ch & 1) * 2304;
        {
            int row = t >> 2, seg = t & 3;
            int gj = kv0 + row;
            int cg2 = gj < KVLEN ? gj : KVLEN - 1;
            uint32_t dst = (uint32_t)__cvta_generic_to_shared(&K[row * 20 + seg * 4]);
            cp_async16(dst, kbp + (size_t)cg2 * DQK + seg * 8, gj < KVLEN ? 16 : 0);
        }
        #pragma unroll
        for (int i = 0; i < 2; i++) {
            int idx = t + i * 256;
            int row = idx >> 3, seg = idx & 7;
            uint32_t dst = (uint32_t)__cvta_generic_to_shared(&V[row * 36 + seg * 4]);
            cp_async16(dst, vbp + (size_t)row * KVPAD + kv0 + seg * 8, 16);
        }
        asm volatile("cp.async.commit_group;" ::: "memory");
    };

    issue(0);

    for (int ch = 0; ch < nch; ch++) {
        int kv0 = ch << 6;
        if (ch + 1 < nch) {
            issue(ch + 1);
            asm volatile("cp.async.wait_group 1;" ::: "memory");
        } else {
            asm volatile("cp.async.wait_group 0;" ::: "memory");
        }
        __syncthreads();

        uint32_t* K = Kb0 + (ch & 1) * 1280;
        uint32_t* V = Vb0 + (ch & 1) * 2304;

        float4 s[8];
        #pragma unroll
        for (int j = 0; j < 8; j++) s[j] = make_float4(0.f, 0.f, 0.f, 0.f);
        #pragma unroll
        for (int kb = 0; kb < 2; kb++) {
            #pragma unroll
            for (int j = 0; j < 8; j++) {
                int cn = j * 8 + g;
                uint32_t bf[2] = { K[cn * 20 + 8 * kb + tg], K[cn * 20 + 8 * kb + 4 + tg] };
                mma16(s[j], qf[kb], bf);
            }
        }

        if (kv0 + 63 > warp_min_row + VKV || kv0 + 63 >= KVLEN) {
            #pragma unroll
            for (int j = 0; j < 8; j++) {
                int c0 = kv0 + j * 8 + 2 * tg;
                int c1 = c0 + 1;
                s[j].x = (c0 <= row_lo + VKV && c0 < KVLEN) ? s[j].x : -INFINITY;
                s[j].y = (c1 <= row_lo + VKV && c1 < KVLEN) ? s[j].y : -INFINITY;
                s[j].z = (c0 <= row_hi + VKV && c0 < KVLEN) ? s[j].z : -INFINITY;
                s[j].w = (c1 <= row_hi + VKV && c1 < KVLEN) ? s[j].w : -INFINITY;
            }
        }

        float mx_lo = -INFINITY, mx_hi = -INFINITY;
        #pragma unroll
        for (int j = 0; j < 8; j++) {
            mx_lo = fmaxf(mx_lo, fmaxf(s[j].x, s[j].y));
            mx_hi = fmaxf(mx_hi, fmaxf(s[j].z, s[j].w));
        }
        mx_lo = fmaxf(mx_lo, __shfl_xor_sync(FULLM, mx_lo, 1));
        mx_lo = fmaxf(mx_lo, __shfl_xor_sync(FULLM, mx_lo, 2));
        mx_hi = fmaxf(mx_hi, __shfl_xor_sync(FULLM, mx_hi, 1));
        mx_hi = fmaxf(mx_hi, __shfl_xor_sync(FULLM, mx_hi, 2));
        float mn_lo = fmaxf(m_lo, mx_lo);
        float mn_hi = fmaxf(m_hi, mx_hi);
        float corr_lo = __expf(m_lo - mn_lo);
        float corr_hi = __expf(m_hi - mn_hi);

        float ps_lo = 0.f, ps_hi = 0.f;
        #pragma unroll
        for (int j = 0; j < 8; j++) {
            s[j].x = __expf(s[j].x - mn_lo);
            s[j].y = __expf(s[j].y - mn_lo);
            s[j].z = __expf(s[j].z - mn_hi);
            s[j].w = __expf(s[j].w - mn_hi);
            ps_lo += s[j].x + s[j].y;
            ps_hi += s[j].z + s[j].w;
        }
        ps_lo += __shfl_xor_sync(FULLM, ps_lo, 1);
        ps_lo += __shfl_xor_sync(FULLM, ps_lo, 2);
        ps_hi += __shfl_xor_sync(FULLM, ps_hi, 1);
        ps_hi += __shfl_xor_sync(FULLM, ps_hi, 2);
        l_lo = l_lo * corr_lo + ps_lo;
        l_hi = l_hi * corr_hi + ps_hi;
        m_lo = mn_lo; m_hi = mn_hi;
        #pragma unroll
        for (int j = 0; j < 8; j++) {
            z[j].x *= corr_lo; z[j].y *= corr_lo;
            z[j].z *= corr_hi; z[j].w *= corr_hi;
        }

        #pragma unroll
        for (int kb = 0; kb < 4; kb++) {
            uint32_t af[4];
            af[0] = packh2(s[2 * kb].x,     s[2 * kb].y);
            af[1] = packh2(s[2 * kb].z,     s[2 * kb].w);
            af[2] = packh2(s[2 * kb + 1].x, s[2 * kb + 1].y);
            af[3] = packh2(s[2 * kb + 1].z, s[2 * kb + 1].w);
            #pragma unroll
            for (int j = 0; j < 8; j++) {
                int cn = j * 8 + g;
                uint32_t bf[2] = { V[cn * 36 + 8 * kb + tg], V[cn * 36 + 8 * kb + 4 + tg] };
                mma16(z[j], af, bf);
            }
        }
        __syncthreads();
    }

    float li_lo = 1.f / l_lo;
    float li_hi = 1.f / l_hi;
    __half* zlo = g_zh + ((size_t)b * SEQ + row_lo) * NOV + h * RATIO;
    __half* zhi = g_zh + ((size_t)b * SEQ + row_hi) * NOV + h * RATIO;
    #pragma unroll
    for (int j = 0; j < 8; j++) {
        int col = j * 8 + 2 * tg;
        *(uint32_t*)&zlo[col] = packh2(z[j].x * li_lo, z[j].y * li_lo);
        *(uint32_t*)&zhi[col] = packh2(z[j].z * li_hi, z[j].w * li_hi);
    }
}

// ---------------- output GEMM: fp16 mma, BK=64 XOR-swizzled, 3-stage. BM=64, BN=128 ----
// Stage: A[64x32] + B[128x32] = 6144 words (24 KB). 32 k-iters.
__global__ void __launch_bounds__(256, 2) out_gemm_kernel(float* __restrict__ out)
{
    extern __shared__ uint32_t dsm[];
    uint32_t smb = (uint32_t)__cvta_generic_to_shared(dsm);

    int n0 = blockIdx.x * 128, r0 = blockIdx.y * 64;
    int t = threadIdx.x;
    int w = t >> 5, lane = t & 31;
    int g = lane >> 2, tg = lane & 3;
    int wm = w >> 1, wn = w & 1;

    float4 acc[8];
    #pragma unroll
    for (int j = 0; j < 8; j++) acc[j] = make_float4(0.f, 0.f, 0.f, 0.f);

    const __half* Abase = g_zh + (size_t)r0 * NOV;
    const __half* Bbase = g_woh + (size_t)n0 * NOV;

    int a_r = lane & 15;
    int a_chi = (lane >> 4) & 1;
    int b_r = (lane & 7) + ((lane & 16) ? 8 : 0);
    int b_chi = (lane >> 3) & 1;

    auto issue = [&](int kt) {
        int s = (kt % 3) * 6144;
        int k0 = kt * 64;
        #pragma unroll
        for (int i = 0; i < 2; i++) {   // A: 512 chunks
            int idx = t + i * 256;
            int row = idx >> 3, c = idx & 7;
            int sw = ((c ^ (row & 7)) << 2);
            cp_async16(smb + (s + row * 32 + sw) * 4,
                       Abase + (size_t)row * NOV + k0 + c * 8, 16);
        }
        #pragma unroll
        for (int i = 0; i < 4; i++) {   // B: 1024 chunks
            int idx = t + i * 256;
            int row = idx >> 3, c = idx & 7;
            int sw = ((c ^ (row & 7)) << 2);
            cp_async16(smb + (s + 2048 + row * 32 + sw) * 4,
                       Bbase + (size_t)row * NOV + k0 + c * 8, 16);
        }
        asm volatile("cp.async.commit_group;" ::: "memory");
    };

    issue(0); issue(1);
    for (int kt = 0; kt < 32; kt++) {
        if (kt < 31) asm volatile("cp.async.wait_group 1;" ::: "memory");
        else         asm volatile("cp.async.wait_group 0;" ::: "memory");
        __syncthreads();
        if (kt + 2 < 32) issue(kt + 2);

        uint32_t sA = smb + ((kt % 3) * 6144) * 4;
        uint32_t sB = sA + 2048 * 4;
        #pragma unroll
        for (int kb = 0; kb < 4; kb++) {
            uint32_t af[4];
            {
                int row = wm * 16 + a_r;
                int c = kb * 2 + a_chi;
                ldsm4(af[0], af[1], af[2], af[3],
                      sA + (row * 32 + ((c ^ (row & 7)) << 2)) * 4);
            }
            #pragma unroll
            for (int p = 0; p < 4; p++) {
                int row = wn * 64 + p * 16 + b_r;
                int c = kb * 2 + b_chi;
                uint32_t bf0, bf1, bf2, bf3;
                ldsm4(bf0, bf1, bf2, bf3,
                      sB + (row * 32 + ((c ^ (row & 7)) << 2)) * 4);
                uint32_t b01[2] = { bf0, bf1 };
                uint32_t b23[2] = { bf2, bf3 };
                mma16(acc[2 * p],     af, b01);
                mma16(acc[2 * p + 1], af, b23);
            }
        }
    }

    int row0 = r0 + wm * 16 + g;
    #pragma unroll
    for (int j = 0; j < 8; j++) {
        int n = n0 + wn * 64 + j * 8 + tg * 2;
        *(float2*)&out[(size_t)row0 * DMODEL + n] = make_float2(acc[j].x, acc[j].y);
        *(float2*)&out[(size_t)(row0 + 8) * DMODEL + n] = make_float2(acc[j].z, acc[j].w);
    }
}

// ---------------- launch ----------------
extern "C" void kernel_launch(void* const* d_in, const int* in_sizes, int n_in,
                              void* d_out, int out_size)
{
    const float* resid = (const float*)d_in[0];
    const float* Wq    = (const float*)d_in[1];
    const float* Wk    = (const float*)d_in[2];
    const float* Wv    = (const float*)d_in[3];
    const float* Wo    = (const float*)d_in[4];
    const float* bq    = (const float*)d_in[5];
    const float* bk    = (const float*)d_in[6];
    const float* bv    = (const float*)d_in[7];
    const float* vk    = (const float*)d_in[8];
    const float* vv    = (const float*)d_in[9];
    float* out = (float*)d_out;

    const int ATTN_SMEM = (2 * 1280 + 2 * 2304) * 4;   // 28672
    const int QKV_SMEM  = 3 * 8192 * 4;                // 98304 (pipeline > epilogue 67584)
    const int OUT_SMEM  = 3 * 6144 * 4;                // 73728
    static int smem_set = 0;
    if (!smem_set) {
        cudaFuncSetAttribute(attn_mma_kernel,
                             cudaFuncAttributeMaxDynamicSharedMemorySize, ATTN_SMEM);
        cudaFuncSetAttribute(qkv_gemm_kernel,
                             cudaFuncAttributeMaxDynamicSharedMemorySize, QKV_SMEM);
        cudaFuncSetAttribute(out_gemm_kernel,
                             cudaFuncAttributeMaxDynamicSharedMemorySize, OUT_SMEM);
        smem_set = 1;
    }

    prep_kernel<<<1024, 256>>>(resid, Wv, vk, vv);
    transpose_qk_kernel<<<dim3(32, 32, 2), dim3(32, 32)>>>(Wq, Wk);
    transpose_wo_kernel<<<dim3(64, 32), dim3(32, 32)>>>(Wo);
    qkv_gemm_kernel<<<dim3(32, 16), 256, QKV_SMEM>>>(bq, bk, bv);
    attn_mma_kernel<<<dim3(8, 32, 2), 256, ATTN_SMEM>>>();
    out_gemm_kernel<<<dim3(8, 32), 256, OUT_SMEM>>>(out);
}

// round 15
// speedup vs baseline: 1.2810x; 1.0384x over previous
#include <cuda_runtime.h>
#include <cuda_fp16.h>
#include <math.h>
#include <stdint.h>

#define SEQ    1024
#define DMODEL 1024
#define NQK    32
#define DQK    32
#define NOV    2048
#define BATCH  2
#define VKV    16
#define KVLEN  (SEQ + VKV)   /* 1040 */
#define KVPAD  1088          /* padded kv pitch for g_vh */
#define RATIO  (NOV / NQK)   /* 64 */
#define FULLM  0xFFFFFFFFu

// ---------------- scratch (static device globals; no allocation) ----------------
__device__ __half g_qh[(size_t)BATCH * NQK * SEQ   * DQK];   // [b][h][s][d], pre-scaled log2e/sqrt(32)
__device__ __half g_kh[(size_t)BATCH * NQK * KVLEN * DQK];   // [b][h][kv][d]
__device__ __half g_vh[(size_t)BATCH * NOV * KVPAD];         // [b][n][kv]  (transposed, padded)
__device__ __half g_zh[(size_t)BATCH * SEQ * NOV];           // [bs][n]
__device__ __half g_xh[(size_t)BATCH * SEQ * DMODEL];        // resid as half [m][k]
__device__ __half g_bh[(size_t)4096 * DMODEL];               // [Wq^T | Wk^T | Wv] as [n][k]
__device__ __half g_woh[(size_t)DMODEL * NOV];               // Wo^T as [n][k]
__device__ float  g_sin[SEQ * 16];
__device__ float  g_cos[SEQ * 16];

// ---------------- helpers ----------------
__device__ __forceinline__ uint32_t packh2(float lo, float hi) {
    __half2 h = __floats2half2_rn(lo, hi);
    return *(uint32_t*)&h;
}
__device__ __forceinline__ float ex2(float x) {
    float y;
    asm("ex2.approx.f32 %0, %1;" : "=f"(y) : "f"(x));
    return y;
}
__device__ __forceinline__ void mma16(float4& d, const uint32_t* a, const uint32_t* b) {
    asm volatile(
        "mma.sync.aligned.m16n8k16.row.col.f32.f16.f16.f32 "
        "{%0,%1,%2,%3}, {%4,%5,%6,%7}, {%8,%9}, {%0,%1,%2,%3};\n"
        : "+f"(d.x), "+f"(d.y), "+f"(d.z), "+f"(d.w)
        : "r"(a[0]), "r"(a[1]), "r"(a[2]), "r"(a[3]), "r"(b[0]), "r"(b[1]));
}
__device__ __forceinline__ void cp_async16(uint32_t dst_smem, const void* src, int src_bytes) {
    asm volatile("cp.async.cg.shared.global [%0], [%1], 16, %2;"
                 :: "r"(dst_smem), "l"(src), "r"(src_bytes));
}
__device__ __forceinline__ void ldsm4(uint32_t& r0, uint32_t& r1, uint32_t& r2, uint32_t& r3,
                                      uint32_t addr) {
    asm volatile("ldmatrix.sync.aligned.m8n8.x4.shared.b16 {%0,%1,%2,%3}, [%4];"
                 : "=r"(r0), "=r"(r1), "=r"(r2), "=r"(r3) : "r"(addr));
}

// ---------------- prep: converts + rotary + virtual kv  AND  Wq/Wk transpose ---------
__global__ void __launch_bounds__(256) prep_kernel(
    const float* __restrict__ resid, const float* __restrict__ Wv,
    const float* __restrict__ vk, const float* __restrict__ vv,
    const float* __restrict__ Wq, const float* __restrict__ Wk)
{
    int bid = blockIdx.x;
    int t = threadIdx.x;
    if (bid < 1024) {
        int i = bid * 256 + t;
        size_t base = (size_t)i * 8;
        float4 a0 = *(const float4*)(resid + base);
        float4 a1 = *(const float4*)(resid + base + 4);
        *(uint4*)&g_xh[base] = make_uint4(packh2(a0.x, a0.y), packh2(a0.z, a0.w),
                                          packh2(a1.x, a1.y), packh2(a1.z, a1.w));
        float4 b0 = *(const float4*)(Wv + base);
        float4 b1 = *(const float4*)(Wv + base + 4);
        *(uint4*)&g_bh[(size_t)2048 * DMODEL + base] =
            make_uint4(packh2(b0.x, b0.y), packh2(b0.z, b0.w),
                       packh2(b1.x, b1.y), packh2(b1.z, b1.w));
        if (i < SEQ * 16) {
            int pos = i >> 4, jm = i & 15;
            float freq = powf(10000.0f, (float)jm * (1.0f / 16.0f));
            float ang = (float)pos / freq;
            g_sin[i] = sinf(ang);
            g_cos[i] = cosf(ang);
        }
        if (i < BATCH * NQK * VKV * DQK) {
            int d  = i & 31;
            int tt = (i >> 5) & 15;
            int h  = (i >> 9) & 31;
            int b  = i >> 14;
            g_kh[(((size_t)b * NQK + h) * KVLEN + SEQ + tt) * DQK + d] =
                __float2half(vk[((size_t)tt * NQK + h) * DQK + d]);
        }
        if (i < BATCH * NOV * 64) {
            int c = 1024 + (i & 63);
            int n = (i >> 6) & 2047;
            int b = i >> 17;
            float val = (c < KVLEN) ? vv[(size_t)(c - SEQ) * NOV + n] : 0.f;
            g_vh[((size_t)b * NOV + n) * KVPAD + c] = __float2half(val);
        }
    } else {
        __shared__ float sm[64][33];
        int b2 = bid - 1024;
        int z  = b2 >> 9;              // 0=Wq, 1=Wk
        int h  = (b2 >> 4) & 31;
        int m0 = (b2 & 15) * 64;
        const float* W = z ? Wk : Wq;
        #pragma unroll
        for (int i = 0; i < 2; i++) {
            int row = (t >> 3) + i * 32;
            int c4 = (t & 7) * 4;
            float4 v = *(const float4*)(W + ((size_t)h * 1024 + m0 + row) * 32 + c4);
            sm[row][c4] = v.x; sm[row][c4 + 1] = v.y;
            sm[row][c4 + 2] = v.z; sm[row][c4 + 3] = v.w;
        }
        __syncthreads();
        int d = t >> 3, mc = t & 7;
        __half h8[8];
        #pragma unroll
        for (int i = 0; i < 8; i++) h8[i] = __float2half(sm[mc * 8 + i][d]);
        *(uint4*)&g_bh[((size_t)z * 1024 + h * 32 + d) * DMODEL + m0 + mc * 8] =
            *(uint4*)h8;
    }
}

// ---------------- fused QKV GEMM + (nt==32) Wo transpose overlap ---------------------
__global__ void __launch_bounds__(256, 2) qkv_gemm_kernel(
    const float* __restrict__ bq, const float* __restrict__ bk,
    const float* __restrict__ bv, const float* __restrict__ Wo)
{
    extern __shared__ uint32_t dsm[];
    int nt = blockIdx.x;
    int t = threadIdx.x;

    if (nt == 32) {
        // Wo transpose: [k=2048][n=1024] f32 -> g_woh[n][k] half.
        // Per block: k slab [kb0, kb0+128) x n [0, 1024) = 64 tiles of 64k x 32n.
        float (*Ts)[33] = (float(*)[33])dsm;
        int kb0 = blockIdx.y * 128;
        #pragma unroll 1
        for (int tt = 0; tt < 64; tt++) {
            int k0 = kb0 + (tt & 1) * 64;
            int n0 = (tt >> 1) * 32;
            __syncthreads();
            #pragma unroll
            for (int i = 0; i < 2; i++) {
                int row = (t >> 3) + i * 32;
                int c4 = (t & 7) * 4;
                float4 v = *(const float4*)(Wo + (size_t)(k0 + row) * DMODEL + n0 + c4);
                Ts[row][c4] = v.x; Ts[row][c4 + 1] = v.y;
                Ts[row][c4 + 2] = v.z; Ts[row][c4 + 3] = v.w;
            }
            __syncthreads();
            int d = t >> 3, mc = t & 7;
            __half h8[8];
            #pragma unroll
            for (int i = 0; i < 8; i++) h8[i] = __float2half(Ts[mc * 8 + i][d]);
            *(uint4*)&g_woh[(size_t)(n0 + d) * NOV + k0 + mc * 8] = *(uint4*)h8;
        }
        return;
    }

    float (*Cs)[132] = (float(*)[132])dsm;
    __half* Ch = (__half*)dsm;
    uint32_t smb = (uint32_t)__cvta_generic_to_shared(dsm);

    int n0 = nt * 128;
    int r0 = blockIdx.y * 128;
    int region = (nt < 8) ? 0 : (nt < 16) ? 1 : 2;
    int cb = (region == 0) ? n0 : (region == 1) ? n0 - 1024 : n0 - 2048;
    int hbase = cb >> 5;

    int w = t >> 5, lane = t & 31;
    int g = lane >> 2, tg = lane & 3;
    int wm = w >> 1, wn = w & 1;

    float4 acc[2][8];
    #pragma unroll
    for (int i = 0; i < 2; i++)
        #pragma unroll
        for (int j = 0; j < 8; j++) acc[i][j] = make_float4(0.f, 0.f, 0.f, 0.f);

    const __half* Abase = g_xh + (size_t)r0 * DMODEL;
    const __half* Bbase = g_bh + (size_t)n0 * DMODEL;

    int a_r = lane & 15;
    int a_chi = (lane >> 4) & 1;
    int b_r = (lane & 7) + ((lane & 16) ? 8 : 0);
    int b_chi = (lane >> 3) & 1;

    auto issue = [&](int kt) {
        int s = (kt % 3) * 8192;
        int k0 = kt * 64;
        #pragma unroll
        for (int i = 0; i < 4; i++) {
            int idx = t + i * 256;
            int row = idx >> 3, c = idx & 7;
            int sw = ((c ^ (row & 7)) << 2);
            cp_async16(smb + (s + row * 32 + sw) * 4,
                       Abase + (size_t)row * DMODEL + k0 + c * 8, 16);
            cp_async16(smb + (s + 4096 + row * 32 + sw) * 4,
                       Bbase + (size_t)row * DMODEL + k0 + c * 8, 16);
        }
        asm volatile("cp.async.commit_group;" ::: "memory");
    };

    issue(0); issue(1);
    for (int kt = 0; kt < 16; kt++) {
        if (kt < 15) asm volatile("cp.async.wait_group 1;" ::: "memory");
        else         asm volatile("cp.async.wait_group 0;" ::: "memory");
        __syncthreads();
        if (kt + 2 < 16) issue(kt + 2);

        uint32_t sA = smb + ((kt % 3) * 8192) * 4;
        uint32_t sB = sA + 4096 * 4;
        #pragma unroll
        for (int kb = 0; kb < 4; kb++) {
            uint32_t af[2][4];
            #pragma unroll
            for (int i = 0; i < 2; i++) {
                int row = wm * 32 + i * 16 + a_r;
                int c = kb * 2 + a_chi;
                ldsm4(af[i][0], af[i][1], af[i][2], af[i][3],
                      sA + (row * 32 + ((c ^ (row & 7)) << 2)) * 4);
            }
            #pragma unroll
            for (int p = 0; p < 4; p++) {
                int row = wn * 64 + p * 16 + b_r;
                int c = kb * 2 + b_chi;
                uint32_t bf0, bf1, bf2, bf3;
                ldsm4(bf0, bf1, bf2, bf3,
                      sB + (row * 32 + ((c ^ (row & 7)) << 2)) * 4);
                uint32_t b01[2] = { bf0, bf1 };
                uint32_t b23[2] = { bf2, bf3 };
                mma16(acc[0][2 * p],     af[0], b01);
                mma16(acc[1][2 * p],     af[1], b01);
                mma16(acc[0][2 * p + 1], af[0], b23);
                mma16(acc[1][2 * p + 1], af[1], b23);
            }
        }
    }
    __syncthreads();

    if (region == 2) {
        int nv0 = cb;
        #pragma unroll
        for (int i = 0; i < 2; i++) {
            int rl = wm * 32 + i * 16 + g;
            #pragma unroll
            for (int j = 0; j < 8; j++) {
                int n = wn * 64 + j * 8 + tg * 2;
                float2 bvv = *(const float2*)(bv + nv0 + n);
                Ch[(size_t)n       * 136 + rl    ] = __float2half(acc[i][j].x + bvv.x);
                Ch[(size_t)(n + 1) * 136 + rl    ] = __float2half(acc[i][j].y + bvv.y);
                Ch[(size_t)n       * 136 + rl + 8] = __float2half(acc[i][j].z + bvv.x);
                Ch[(size_t)(n + 1) * 136 + rl + 8] = __float2half(acc[i][j].w + bvv.y);
            }
        }
        __syncthreads();
        int b = r0 >> 10, s0 = r0 & 1023;
        #pragma unroll
        for (int p = 0; p < 8; p++) {
            int idx = t + p * 256;
            int n = idx >> 4, c8 = (idx & 15) * 8;
            uint4 v = *(uint4*)&Ch[(size_t)n * 136 + c8];
            *(uint4*)&g_vh[((size_t)b * NOV + nv0 + n) * KVPAD + s0 + c8] = v;
        }
    } else {
        const float* bias = (region == 0) ? bq : bk;
        #pragma unroll
        for (int i = 0; i < 2; i++) {
            int rr = wm * 32 + i * 16 + g;
            #pragma unroll
            for (int j = 0; j < 8; j++) {
                int c = wn * 64 + j * 8 + tg * 2;
                float b0 = bias[cb + c];
                float b1 = bias[cb + c + 1];
                Cs[rr    ][c    ] = acc[i][j].x + b0;
                Cs[rr    ][c + 1] = acc[i][j].y + b1;
                Cs[rr + 8][c    ] = acc[i][j].z + b0;
                Cs[rr + 8][c + 1] = acc[i][j].w + b1;
            }
        }
        __syncthreads();

        const float qscale = 0.17677669529663687f * 1.4426950408889634f;  // log2e/sqrt(32)
        float sc = (region == 0) ? qscale : 1.f;
        #pragma unroll
        for (int p = 0; p < 2; p++) {
            int idx = t + p * 256;
            int r = idx >> 2, hh = idx & 3;
            int grow = r0 + r;
            int bb = grow >> 10, pos = grow & 1023;
            int h = hbase + hh;
            const float* base = &Cs[r][hh * 32];
            __half* dst = (region == 0)
                ? g_qh + (((size_t)bb * NQK + h) * SEQ   + pos) * DQK
                : g_kh + (((size_t)bb * NQK + h) * KVLEN + pos) * DQK;
            #pragma unroll
            for (int c = 0; c < 32; c++) {
                float val  = base[c];
                float flip = (c < 16) ? -base[c + 16] : base[c - 16];
                int jm = c & 15;
                float sn = g_sin[pos * 16 + jm];
                float cs = g_cos[pos * 16 + jm];
                dst[c] = __float2half((val * cs + flip * sn) * sc);
            }
        }
    }
}

// ---------------- attention: fp16 mma flash, base-2 softmax ----------------
__global__ void __launch_bounds__(256, 2) attn_mma_kernel()
{
    extern __shared__ uint32_t smem[];
    uint32_t* Kb0 = smem;
    uint32_t* Vb0 = smem + 2 * 1280;

    int qt = 7 - blockIdx.x;
    int h = blockIdx.y, b = blockIdx.z;
    int i0 = qt * 128;
    int t = threadIdx.x, w = t >> 5, lane = t & 31;
    int g = lane >> 2, tg = lane & 3;

    const __half* kbp = g_kh + ((size_t)b * NQK + h) * KVLEN * DQK;
    const __half* vbp = g_vh + ((size_t)b * NOV + h * RATIO) * KVPAD;

    uint32_t qf[2][4];
    {
        const __half* qb = g_qh + (((size_t)b * NQK + h) * SEQ + i0 + w * 16) * DQK;
        #pragma unroll
        for (int kb = 0; kb < 2; kb++) {
            qf[kb][0] = *(const uint32_t*)(qb + (size_t)g       * DQK + kb * 16 + 2 * tg);
            qf[kb][1] = *(const uint32_t*)(qb + (size_t)(g + 8) * DQK + kb * 16 + 2 * tg);
            qf[kb][2] = *(const uint32_t*)(qb + (size_t)g       * DQK + kb * 16 + 8 + 2 * tg);
            qf[kb][3] = *(const uint32_t*)(qb + (size_t)(g + 8) * DQK + kb * 16 + 8 + 2 * tg);
        }
    }

    float m_lo = -INFINITY, m_hi = -INFINITY, l_lo = 0.f, l_hi = 0.f;
    float4 z[8];
    #pragma unroll
    for (int j = 0; j < 8; j++) z[j] = make_float4(0.f, 0.f, 0.f, 0.f);

    int row_lo = i0 + w * 16 + g;
    int row_hi = row_lo + 8;
    int warp_min_row = i0 + w * 16;

    int jlim = i0 + 128 + VKV;
    if (jlim > KVLEN) jlim = KVLEN;
    int nch = (jlim + 63) >> 6;

    auto issue = [&](int ch) {
        int kv0 = ch << 6;
        uint32_t* K = Kb0 + (ch & 1) * 1280;
        uint32_t* V = Vb0 + (ch & 1) * 2304;
        {
            int row = t >> 2, seg = t & 3;
            int gj = kv0 + row;
            int cg2 = gj < KVLEN ? gj : KVLEN - 1;
            uint32_t dst = (uint32_t)__cvta_generic_to_shared(&K[row * 20 + seg * 4]);
            cp_async16(dst, kbp + (size_t)cg2 * DQK + seg * 8, gj < KVLEN ? 16 : 0);
        }
        #pragma unroll
        for (int i = 0; i < 2; i++) {
            int idx = t + i * 256;
            int row = idx >> 3, seg = idx & 7;
            uint32_t dst = (uint32_t)__cvta_generic_to_shared(&V[row * 36 + seg * 4]);
            cp_async16(dst, vbp + (size_t)row * KVPAD + kv0 + seg * 8, 16);
        }
        asm volatile("cp.async.commit_group;" ::: "memory");
    };

    issue(0);

    for (int ch = 0; ch < nch; ch++) {
        int kv0 = ch << 6;
        if (ch + 1 < nch) {
            issue(ch + 1);
            asm volatile("cp.async.wait_group 1;" ::: "memory");
        } else {
            asm volatile("cp.async.wait_group 0;" ::: "memory");
        }
        __syncthreads();

        uint32_t* K = Kb0 + (ch & 1) * 1280;
        uint32_t* V = Vb0 + (ch & 1) * 2304;

        float4 s[8];
        #pragma unroll
        for (int j = 0; j < 8; j++) s[j] = make_float4(0.f, 0.f, 0.f, 0.f);
        #pragma unroll
        for (int kb = 0; kb < 2; kb++) {
            #pragma unroll
            for (int j = 0; j < 8; j++) {
                int cn = j * 8 + g;
                uint32_t bf[2] = { K[cn * 20 + 8 * kb + tg], K[cn * 20 + 8 * kb + 4 + tg] };
                mma16(s[j], qf[kb], bf);
            }
        }

        if (kv0 + 63 > warp_min_row + VKV || kv0 + 63 >= KVLEN) {
            #pragma unroll
            for (int j = 0; j < 8; j++) {
                int c0 = kv0 + j * 8 + 2 * tg;
                int c1 = c0 + 1;
                s[j].x = (c0 <= row_lo + VKV && c0 < KVLEN) ? s[j].x : -INFINITY;
                s[j].y = (c1 <= row_lo + VKV && c1 < KVLEN) ? s[j].y : -INFINITY;
                s[j].z = (c0 <= row_hi + VKV && c0 < KVLEN) ? s[j].z : -INFINITY;
                s[j].w = (c1 <= row_hi + VKV && c1 < KVLEN) ? s[j].w : -INFINITY;
            }
        }

        float mx_lo = -INFINITY, mx_hi = -INFINITY;
        #pragma unroll
        for (int j = 0; j < 8; j++) {
            mx_lo = fmaxf(mx_lo, fmaxf(s[j].x, s[j].y));
            mx_hi = fmaxf(mx_hi, fmaxf(s[j].z, s[j].w));
        }
        mx_lo = fmaxf(mx_lo, __shfl_xor_sync(FULLM, mx_lo, 1));
        mx_lo = fmaxf(mx_lo, __shfl_xor_sync(FULLM, mx_lo, 2));
        mx_hi = fmaxf(mx_hi, __shfl_xor_sync(FULLM, mx_hi, 1));
        mx_hi = fmaxf(mx_hi, __shfl_xor_sync(FULLM, mx_hi, 2));
        float mn_lo = fmaxf(m_lo, mx_lo);
        float mn_hi = fmaxf(m_hi, mx_hi);
        float corr_lo = ex2(m_lo - mn_lo);
        float corr_hi = ex2(m_hi - mn_hi);

        float ps_lo = 0.f, ps_hi = 0.f;
        #pragma unroll
        for (int j = 0; j < 8; j++) {
            s[j].x = ex2(s[j].x - mn_lo);
            s[j].y = ex2(s[j].y - mn_lo);
            s[j].z = ex2(s[j].z - mn_hi);
            s[j].w = ex2(s[j].w - mn_hi);
            ps_lo += s[j].x + s[j].y;
            ps_hi += s[j].z + s[j].w;
        }
        ps_lo += __shfl_xor_sync(FULLM, ps_lo, 1);
        ps_lo += __shfl_xor_sync(FULLM, ps_lo, 2);
        ps_hi += __shfl_xor_sync(FULLM, ps_hi, 1);
        ps_hi += __shfl_xor_sync(FULLM, ps_hi, 2);
        l_lo = l_lo * corr_lo + ps_lo;
        l_hi = l_hi * corr_hi + ps_hi;
        m_lo = mn_lo; m_hi = mn_hi;
        #pragma unroll
        for (int j = 0; j < 8; j++) {
            z[j].x *= corr_lo; z[j].y *= corr_lo;
            z[j].z *= corr_hi; z[j].w *= corr_hi;
        }

        #pragma unroll
        for (int kb = 0; kb < 4; kb++) {
            uint32_t af[4];
            af[0] = packh2(s[2 * kb].x,     s[2 * kb].y);
            af[1] = packh2(s[2 * kb].z,     s[2 * kb].w);
            af[2] = packh2(s[2 * kb + 1].x, s[2 * kb + 1].y);
            af[3] = packh2(s[2 * kb + 1].z, s[2 * kb + 1].w);
            #pragma unroll
            for (int j = 0; j < 8; j++) {
                int cn = j * 8 + g;
                uint32_t bf[2] = { V[cn * 36 + 8 * kb + tg], V[cn * 36 + 8 * kb + 4 + tg] };
                mma16(z[j], af, bf);
            }
        }
        __syncthreads();
    }

    float li_lo = 1.f / l_lo;
    float li_hi = 1.f / l_hi;
    __half* zlo = g_zh + ((size_t)b * SEQ + row_lo) * NOV + h * RATIO;
    __half* zhi = g_zh + ((size_t)b * SEQ + row_hi) * NOV + h * RATIO;
    #pragma unroll
    for (int j = 0; j < 8; j++) {
        int col = j * 8 + 2 * tg;
        *(uint32_t*)&zlo[col] = packh2(z[j].x * li_lo, z[j].y * li_lo);
        *(uint32_t*)&zhi[col] = packh2(z[j].z * li_hi, z[j].w * li_hi);
    }
}

// ---------------- output GEMM: fp16 mma, BK=64 XOR-swizzled, 3-stage. BM=64, BN=128 ----
__global__ void __launch_bounds__(256, 2) out_gemm_kernel(float* __restrict__ out)
{
    extern __shared__ uint32_t dsm[];
    uint32_t smb = (uint32_t)__cvta_generic_to_shared(dsm);

    int n0 = blockIdx.x * 128, r0 = blockIdx.y * 64;
    int t = threadIdx.x;
    int w = t >> 5, lane = t & 31;
    int g = lane >> 2, tg = lane & 3;
    int wm = w >> 1, wn = w & 1;

    float4 acc[8];
    #pragma unroll
    for (int j = 0; j < 8; j++) acc[j] = make_float4(0.f, 0.f, 0.f, 0.f);

    const __half* Abase = g_zh + (size_t)r0 * NOV;
    const __half* Bbase = g_woh + (size_t)n0 * NOV;

    int a_r = lane & 15;
    int a_chi = (lane >> 4) & 1;
    int b_r = (lane & 7) + ((lane & 16) ? 8 : 0);
    int b_chi = (lane >> 3) & 1;

    auto issue = [&](int kt) {
        int s = (kt % 3) * 6144;
        int k0 = kt * 64;
        #pragma unroll
        for (int i = 0; i < 2; i++) {
            int idx = t + i * 256;
            int row = idx >> 3, c = idx & 7;
            int sw = ((c ^ (row & 7)) << 2);
            cp_async16(smb + (s + row * 32 + sw) * 4,
                       Abase + (size_t)row * NOV + k0 + c * 8, 16);
        }
        #pragma unroll
        for (int i = 0; i < 4; i++) {
            int idx = t + i * 256;
            int row = idx >> 3, c = idx & 7;
            int sw = ((c ^ (row & 7)) << 2);
            cp_async16(smb + (s + 2048 + row * 32 + sw) * 4,
                       Bbase + (size_t)row * NOV + k0 + c * 8, 16);
        }
        asm volatile("cp.async.commit_group;" ::: "memory");
    };

    issue(0); issue(1);
    for (int kt = 0; kt < 32; kt++) {
        if (kt < 31) asm volatile("cp.async.wait_group 1;" ::: "memory");
        else         asm volatile("cp.async.wait_group 0;" ::: "memory");
        __syncthreads();
        if (kt + 2 < 32) issue(kt + 2);

        uint32_t sA = smb + ((kt % 3) * 6144) * 4;
        uint32_t sB = sA + 2048 * 4;
        #pragma unroll
        for (int kb = 0; kb < 4; kb++) {
            uint32_t af[4];
            {
                int row = wm * 16 + a_r;
                int c = kb * 2 + a_chi;
                ldsm4(af[0], af[1], af[2], af[3],
                      sA + (row * 32 + ((c ^ (row & 7)) << 2)) * 4);
            }
            #pragma unroll
            for (int p = 0; p < 4; p++) {
                int row = wn * 64 + p * 16 + b_r;
                int c = kb * 2 + b_chi;
                uint32_t bf0, bf1, bf2, bf3;
                ldsm4(bf0, bf1, bf2, bf3,
                      sB + (row * 32 + ((c ^ (row & 7)) << 2)) * 4);
                uint32_t b01[2] = { bf0, bf1 };
                uint32_t b23[2] = { bf2, bf3 };
                mma16(acc[2 * p],     af, b01);
                mma16(acc[2 * p + 1], af, b23);
            }
        }
    }

    int row0 = r0 + wm * 16 + g;
    #pragma unroll
    for (int j = 0; j < 8; j++) {
        int n = n0 + wn * 64 + j * 8 + tg * 2;
        *(float2*)&out[(size_t)row0 * DMODEL + n] = make_float2(acc[j].x, acc[j].y);
        *(float2*)&out[(size_t)(row0 + 8) * DMODEL + n] = make_float2(acc[j].z, acc[j].w);
    }
}

// ---------------- launch ----------------
extern "C" void kernel_launch(void* const* d_in, const int* in_sizes, int n_in,
                              void* d_out, int out_size)
{
    const float* resid = (const float*)d_in[0];
    const float* Wq    = (const float*)d_in[1];
    const float* Wk    = (const float*)d_in[2];
    const float* Wv    = (const float*)d_in[3];
    const float* Wo    = (const float*)d_in[4];
    const float* bq    = (const float*)d_in[5];
    const float* bk    = (const float*)d_in[6];
    const float* bv    = (const float*)d_in[7];
    const float* vk    = (const float*)d_in[8];
    const float* vv    = (const float*)d_in[9];
    float* out = (float*)d_out;

    const int ATTN_SMEM = (2 * 1280 + 2 * 2304) * 4;   // 28672
    const int QKV_SMEM  = 3 * 8192 * 4;                // 98304
    const int OUT_SMEM  = 3 * 6144 * 4;                // 73728
    static int smem_set = 0;
    if (!smem_set) {
        cudaFuncSetAttribute(attn_mma_kernel,
                             cudaFuncAttributeMaxDynamicSharedMemorySize, ATTN_SMEM);
        cudaFuncSetAttribute(qkv_gemm_kernel,
                             cudaFuncAttributeMaxDynamicSharedMemorySize, QKV_SMEM);
        cudaFuncSetAttribute(out_gemm_kernel,
                             cudaFuncAttributeMaxDynamicSharedMemorySize, OUT_SMEM);
        smem_set = 1;
    }

    prep_kernel<<<2048, 256>>>(resid, Wv, vk, vv, Wq, Wk);
    qkv_gemm_kernel<<<dim3(33, 16), 256, QKV_SMEM>>>(bq, bk, bv, Wo);
    attn_mma_kernel<<<dim3(8, 32, 2), 256, ATTN_SMEM>>>();
    out_gemm_kernel<<<dim3(8, 32), 256, OUT_SMEM>>>(out);
}

// round 16
// speedup vs baseline: 1.3062x; 1.0197x over previous
#include <cuda_runtime.h>
#include <cuda_fp16.h>
#include <math.h>
#include <stdint.h>

#define SEQ    1024
#define DMODEL 1024
#define NQK    32
#define DQK    32
#define NOV    2048
#define BATCH  2
#define VKV    16
#define KVLEN  (SEQ + VKV)   /* 1040 */
#define KVPAD  1088          /* padded kv pitch for g_vh */
#define RATIO  (NOV / NQK)   /* 64 */
#define FULLM  0xFFFFFFFFu

// ---------------- scratch (static device globals; no allocation) ----------------
__device__ __half g_qh[(size_t)BATCH * NQK * SEQ   * DQK];   // [b][h][s][d], pre-scaled log2e/sqrt(32)
__device__ __half g_kh[(size_t)BATCH * NQK * KVLEN * DQK];   // [b][h][kv][d]
__device__ __half g_vh[(size_t)BATCH * NOV * KVPAD];         // [b][n][kv]  (transposed, padded)
__device__ __half g_zh[(size_t)BATCH * SEQ * NOV];           // [bs][n]
__device__ __half g_xh[(size_t)BATCH * SEQ * DMODEL];        // resid as half [m][k]
__device__ __half g_bh[(size_t)4096 * DMODEL];               // [Wq^T | Wk^T | Wv] as [n][k]
__device__ __half g_woh[(size_t)DMODEL * NOV];               // Wo^T as [n][k]
__device__ float  g_sin[SEQ * 16];
__device__ float  g_cos[SEQ * 16];

// ---------------- helpers ----------------
__device__ __forceinline__ uint32_t packh2(float lo, float hi) {
    __half2 h = __floats2half2_rn(lo, hi);
    return *(uint32_t*)&h;
}
__device__ __forceinline__ float ex2(float x) {
    float y;
    asm("ex2.approx.f32 %0, %1;" : "=f"(y) : "f"(x));
    return y;
}
__device__ __forceinline__ void mma16(float4& d, const uint32_t* a, const uint32_t* b) {
    asm volatile(
        "mma.sync.aligned.m16n8k16.row.col.f32.f16.f16.f32 "
        "{%0,%1,%2,%3}, {%4,%5,%6,%7}, {%8,%9}, {%0,%1,%2,%3};\n"
        : "+f"(d.x), "+f"(d.y), "+f"(d.z), "+f"(d.w)
        : "r"(a[0]), "r"(a[1]), "r"(a[2]), "r"(a[3]), "r"(b[0]), "r"(b[1]));
}
__device__ __forceinline__ void cp_async16(uint32_t dst_smem, const void* src, int src_bytes) {
    asm volatile("cp.async.cg.shared.global [%0], [%1], 16, %2;"
                 :: "r"(dst_smem), "l"(src), "r"(src_bytes));
}
__device__ __forceinline__ void ldsm4(uint32_t& r0, uint32_t& r1, uint32_t& r2, uint32_t& r3,
                                      uint32_t addr) {
    asm volatile("ldmatrix.sync.aligned.m8n8.x4.shared.b16 {%0,%1,%2,%3}, [%4];"
                 : "=r"(r0), "=r"(r1), "=r"(r2), "=r"(r3) : "r"(addr));
}

// ---------------- prep: converts + rotary + virtual kv  AND  Wq/Wk transpose ---------
__global__ void __launch_bounds__(256) prep_kernel(
    const float* __restrict__ resid, const float* __restrict__ Wv,
    const float* __restrict__ vk, const float* __restrict__ vv,
    const float* __restrict__ Wq, const float* __restrict__ Wk)
{
    int bid = blockIdx.x;
    int t = threadIdx.x;
    if (bid < 1024) {
        int i = bid * 256 + t;
        size_t base = (size_t)i * 8;
        float4 a0 = *(const float4*)(resid + base);
        float4 a1 = *(const float4*)(resid + base + 4);
        *(uint4*)&g_xh[base] = make_uint4(packh2(a0.x, a0.y), packh2(a0.z, a0.w),
                                          packh2(a1.x, a1.y), packh2(a1.z, a1.w));
        float4 b0 = *(const float4*)(Wv + base);
        float4 b1 = *(const float4*)(Wv + base + 4);
        *(uint4*)&g_bh[(size_t)2048 * DMODEL + base] =
            make_uint4(packh2(b0.x, b0.y), packh2(b0.z, b0.w),
                       packh2(b1.x, b1.y), packh2(b1.z, b1.w));
        if (i < SEQ * 16) {
            int pos = i >> 4, jm = i & 15;
            float freq = powf(10000.0f, (float)jm * (1.0f / 16.0f));
            float ang = (float)pos / freq;
            g_sin[i] = sinf(ang);
            g_cos[i] = cosf(ang);
        }
        if (i < BATCH * NQK * VKV * DQK) {
            int d  = i & 31;
            int tt = (i >> 5) & 15;
            int h  = (i >> 9) & 31;
            int b  = i >> 14;
            g_kh[(((size_t)b * NQK + h) * KVLEN + SEQ + tt) * DQK + d] =
                __float2half(vk[((size_t)tt * NQK + h) * DQK + d]);
        }
        if (i < BATCH * NOV * 64) {
            int c = 1024 + (i & 63);
            int n = (i >> 6) & 2047;
            int b = i >> 17;
            float val = (c < KVLEN) ? vv[(size_t)(c - SEQ) * NOV + n] : 0.f;
            g_vh[((size_t)b * NOV + n) * KVPAD + c] = __float2half(val);
        }
    } else {
        __shared__ float sm[64][33];
        int b2 = bid - 1024;
        int z  = b2 >> 9;              // 0=Wq, 1=Wk
        int h  = (b2 >> 4) & 31;
        int m0 = (b2 & 15) * 64;
        const float* W = z ? Wk : Wq;
        #pragma unroll
        for (int i = 0; i < 2; i++) {
            int row = (t >> 3) + i * 32;
            int c4 = (t & 7) * 4;
            float4 v = *(const float4*)(W + ((size_t)h * 1024 + m0 + row) * 32 + c4);
            sm[row][c4] = v.x; sm[row][c4 + 1] = v.y;
            sm[row][c4 + 2] = v.z; sm[row][c4 + 3] = v.w;
        }
        __syncthreads();
        int d = t >> 3, mc = t & 7;
        __half h8[8];
        #pragma unroll
        for (int i = 0; i < 8; i++) h8[i] = __float2half(sm[mc * 8 + i][d]);
        *(uint4*)&g_bh[((size_t)z * 1024 + h * 32 + d) * DMODEL + m0 + mc * 8] =
            *(uint4*)h8;
    }
}

// ---------------- fused QKV GEMM + (nt==32) Wo transpose overlap ---------------------
__global__ void __launch_bounds__(256, 2) qkv_gemm_kernel(
    const float* __restrict__ bq, const float* __restrict__ bk,
    const float* __restrict__ bv, const float* __restrict__ Wo)
{
    extern __shared__ uint32_t dsm[];
    int nt = blockIdx.x;
    int t = threadIdx.x;

    if (nt == 32) {
        // Wo transpose: [k=2048][n=1024] f32 -> g_woh[n][k] half. 64 tiles per block.
        float (*Ts)[33] = (float(*)[33])dsm;
        int kb0 = blockIdx.y * 128;
        #pragma unroll 1
        for (int tt = 0; tt < 64; tt++) {
            int k0 = kb0 + (tt & 1) * 64;
            int n0 = (tt >> 1) * 32;
            __syncthreads();
            #pragma unroll
            for (int i = 0; i < 2; i++) {
                int row = (t >> 3) + i * 32;
                int c4 = (t & 7) * 4;
                float4 v = *(const float4*)(Wo + (size_t)(k0 + row) * DMODEL + n0 + c4);
                Ts[row][c4] = v.x; Ts[row][c4 + 1] = v.y;
                Ts[row][c4 + 2] = v.z; Ts[row][c4 + 3] = v.w;
            }
            __syncthreads();
            int d = t >> 3, mc = t & 7;
            __half h8[8];
            #pragma unroll
            for (int i = 0; i < 8; i++) h8[i] = __float2half(Ts[mc * 8 + i][d]);
            *(uint4*)&g_woh[(size_t)(n0 + d) * NOV + k0 + mc * 8] = *(uint4*)h8;
        }
        return;
    }

    float (*Cs)[132] = (float(*)[132])dsm;
    __half* Ch = (__half*)dsm;
    uint32_t smb = (uint32_t)__cvta_generic_to_shared(dsm);

    int n0 = nt * 128;
    int r0 = blockIdx.y * 128;
    int region = (nt < 8) ? 0 : (nt < 16) ? 1 : 2;
    int cb = (region == 0) ? n0 : (region == 1) ? n0 - 1024 : n0 - 2048;
    int hbase = cb >> 5;

    int w = t >> 5, lane = t & 31;
    int g = lane >> 2, tg = lane & 3;
    int wm = w >> 1, wn = w & 1;

    float4 acc[2][8];
    #pragma unroll
    for (int i = 0; i < 2; i++)
        #pragma unroll
        for (int j = 0; j < 8; j++) acc[i][j] = make_float4(0.f, 0.f, 0.f, 0.f);

    const __half* Abase = g_xh + (size_t)r0 * DMODEL;
    const __half* Bbase = g_bh + (size_t)n0 * DMODEL;

    int a_r = lane & 15;
    int a_chi = (lane >> 4) & 1;
    int b_r = (lane & 7) + ((lane & 16) ? 8 : 0);
    int b_chi = (lane >> 3) & 1;

    auto issue = [&](int kt) {
        int s = (kt % 3) * 8192;
        int k0 = kt * 64;
        #pragma unroll
        for (int i = 0; i < 4; i++) {
            int idx = t + i * 256;
            int row = idx >> 3, c = idx & 7;
            int sw = ((c ^ (row & 7)) << 2);
            cp_async16(smb + (s + row * 32 + sw) * 4,
                       Abase + (size_t)row * DMODEL + k0 + c * 8, 16);
            cp_async16(smb + (s + 4096 + row * 32 + sw) * 4,
                       Bbase + (size_t)row * DMODEL + k0 + c * 8, 16);
        }
        asm volatile("cp.async.commit_group;" ::: "memory");
    };

    issue(0); issue(1);
    for (int kt = 0; kt < 16; kt++) {
        if (kt < 15) asm volatile("cp.async.wait_group 1;" ::: "memory");
        else         asm volatile("cp.async.wait_group 0;" ::: "memory");
        __syncthreads();
        if (kt + 2 < 16) issue(kt + 2);

        uint32_t sA = smb + ((kt % 3) * 8192) * 4;
        uint32_t sB = sA + 4096 * 4;
        #pragma unroll
        for (int kb = 0; kb < 4; kb++) {
            uint32_t af[2][4];
            #pragma unroll
            for (int i = 0; i < 2; i++) {
                int row = wm * 32 + i * 16 + a_r;
                int c = kb * 2 + a_chi;
                ldsm4(af[i][0], af[i][1], af[i][2], af[i][3],
                      sA + (row * 32 + ((c ^ (row & 7)) << 2)) * 4);
            }
            #pragma unroll
            for (int p = 0; p < 4; p++) {
                int row = wn * 64 + p * 16 + b_r;
                int c = kb * 2 + b_chi;
                uint32_t bf0, bf1, bf2, bf3;
                ldsm4(bf0, bf1, bf2, bf3,
                      sB + (row * 32 + ((c ^ (row & 7)) << 2)) * 4);
                uint32_t b01[2] = { bf0, bf1 };
                uint32_t b23[2] = { bf2, bf3 };
                mma16(acc[0][2 * p],     af[0], b01);
                mma16(acc[1][2 * p],     af[1], b01);
                mma16(acc[0][2 * p + 1], af[0], b23);
                mma16(acc[1][2 * p + 1], af[1], b23);
            }
        }
    }
    __syncthreads();

    if (region == 2) {
        int nv0 = cb;
        #pragma unroll
        for (int i = 0; i < 2; i++) {
            int rl = wm * 32 + i * 16 + g;
            #pragma unroll
            for (int j = 0; j < 8; j++) {
                int n = wn * 64 + j * 8 + tg * 2;
                float2 bvv = *(const float2*)(bv + nv0 + n);
                Ch[(size_t)n       * 136 + rl    ] = __float2half(acc[i][j].x + bvv.x);
                Ch[(size_t)(n + 1) * 136 + rl    ] = __float2half(acc[i][j].y + bvv.y);
                Ch[(size_t)n       * 136 + rl + 8] = __float2half(acc[i][j].z + bvv.x);
                Ch[(size_t)(n + 1) * 136 + rl + 8] = __float2half(acc[i][j].w + bvv.y);
            }
        }
        __syncthreads();
        int b = r0 >> 10, s0 = r0 & 1023;
        #pragma unroll
        for (int p = 0; p < 8; p++) {
            int idx = t + p * 256;
            int n = idx >> 4, c8 = (idx & 15) * 8;
            uint4 v = *(uint4*)&Ch[(size_t)n * 136 + c8];
            *(uint4*)&g_vh[((size_t)b * NOV + nv0 + n) * KVPAD + s0 + c8] = v;
        }
    } else {
        const float* bias = (region == 0) ? bq : bk;
        #pragma unroll
        for (int i = 0; i < 2; i++) {
            int rr = wm * 32 + i * 16 + g;
            #pragma unroll
            for (int j = 0; j < 8; j++) {
                int c = wn * 64 + j * 8 + tg * 2;
                float b0 = bias[cb + c];
                float b1 = bias[cb + c + 1];
                Cs[rr    ][c    ] = acc[i][j].x + b0;
                Cs[rr    ][c + 1] = acc[i][j].y + b1;
                Cs[rr + 8][c    ] = acc[i][j].z + b0;
                Cs[rr + 8][c + 1] = acc[i][j].w + b1;
            }
        }
        __syncthreads();

        const float qscale = 0.17677669529663687f * 1.4426950408889634f;  // log2e/sqrt(32)
        float sc = (region == 0) ? qscale : 1.f;
        #pragma unroll
        for (int p = 0; p < 2; p++) {
            int idx = t + p * 256;
            int r = idx >> 2, hh = idx & 3;
            int grow = r0 + r;
            int bb = grow >> 10, pos = grow & 1023;
            int h = hbase + hh;
            const float* base = &Cs[r][hh * 32];
            __half* dst = (region == 0)
                ? g_qh + (((size_t)bb * NQK + h) * SEQ   + pos) * DQK
                : g_kh + (((size_t)bb * NQK + h) * KVLEN + pos) * DQK;
            #pragma unroll
            for (int c = 0; c < 32; c++) {
                float val  = base[c];
                float flip = (c < 16) ? -base[c + 16] : base[c - 16];
                int jm = c & 15;
                float sn = g_sin[pos * 16 + jm];
                float cs = g_cos[pos * 16 + jm];
                dst[c] = __float2half((val * cs + flip * sn) * sc);
            }
        }
    }
}

// ---------------- attention: fp16 mma flash, 3-stage cp.async, ldmatrix frags --------
// smem: K[3][64*20] + V[3][64*36] = 10752 words = 43008 B. 2 CTAs/SM.
__global__ void __launch_bounds__(256, 2) attn_mma_kernel()
{
    extern __shared__ uint32_t smem[];
    uint32_t* Kb0 = smem;                  // per stage 1280 words
    uint32_t* Vb0 = smem + 3 * 1280;       // per stage 2304 words
    uint32_t smbK = (uint32_t)__cvta_generic_to_shared(Kb0);
    uint32_t smbV = (uint32_t)__cvta_generic_to_shared(Vb0);

    int qt = 7 - blockIdx.x;
    int h = blockIdx.y, b = blockIdx.z;
    int i0 = qt * 128;
    int t = threadIdx.x, w = t >> 5, lane = t & 31;
    int g = lane >> 2, tg = lane & 3;

    const __half* kbp = g_kh + ((size_t)b * NQK + h) * KVLEN * DQK;
    const __half* vbp = g_vh + ((size_t)b * NOV + h * RATIO) * KVPAD;

    uint32_t qf[2][4];
    {
        const __half* qb = g_qh + (((size_t)b * NQK + h) * SEQ + i0 + w * 16) * DQK;
        #pragma unroll
        for (int kb = 0; kb < 2; kb++) {
            qf[kb][0] = *(const uint32_t*)(qb + (size_t)g       * DQK + kb * 16 + 2 * tg);
            qf[kb][1] = *(const uint32_t*)(qb + (size_t)(g + 8) * DQK + kb * 16 + 2 * tg);
            qf[kb][2] = *(const uint32_t*)(qb + (size_t)g       * DQK + kb * 16 + 8 + 2 * tg);
            qf[kb][3] = *(const uint32_t*)(qb + (size_t)(g + 8) * DQK + kb * 16 + 8 + 2 * tg);
        }
    }

    float m_lo = -INFINITY, m_hi = -INFINITY, l_lo = 0.f, l_hi = 0.f;
    float4 z[8];
    #pragma unroll
    for (int j = 0; j < 8; j++) z[j] = make_float4(0.f, 0.f, 0.f, 0.f);

    int row_lo = i0 + w * 16 + g;
    int row_hi = row_lo + 8;
    int warp_min_row = i0 + w * 16;

    int jlim = i0 + 128 + VKV;
    if (jlim > KVLEN) jlim = KVLEN;
    int nch = (jlim + 63) >> 6;

    // ldmatrix lane mapping (B-operand fragments), same as GEMMs
    int b_r = (lane & 7) + ((lane & 16) ? 8 : 0);
    int b_chi = (lane >> 3) & 1;

    auto issue = [&](int ch) {
        int kv0 = ch << 6;
        int st = ch % 3;
        {
            int row = t >> 2, seg = t & 3;
            int gj = kv0 + row;
            int cg2 = gj < KVLEN ? gj : KVLEN - 1;
            cp_async16(smbK + (st * 1280 + row * 20 + seg * 4) * 4,
                       kbp + (size_t)cg2 * DQK + seg * 8, gj < KVLEN ? 16 : 0);
        }
        #pragma unroll
        for (int i = 0; i < 2; i++) {
            int idx = t + i * 256;
            int row = idx >> 3, seg = idx & 7;
            cp_async16(smbV + (st * 2304 + row * 36 + seg * 4) * 4,
                       vbp + (size_t)row * KVPAD + kv0 + seg * 8, 16);
        }
        asm volatile("cp.async.commit_group;" ::: "memory");
    };

    issue(0);
    if (nch > 1) issue(1);

    for (int ch = 0; ch < nch; ch++) {
        int kv0 = ch << 6;
        if (ch + 1 < nch) asm volatile("cp.async.wait_group 1;" ::: "memory");
        else              asm volatile("cp.async.wait_group 0;" ::: "memory");
        __syncthreads();
        if (ch + 2 < nch) issue(ch + 2);

        uint32_t sK = smbK + ((ch % 3) * 1280) * 4;
        uint32_t sV = smbV + ((ch % 3) * 2304) * 4;

        // S = Q K^T : 2 kb x 4 ldsm -> 16 mma
        float4 s[8];
        #pragma unroll
        for (int j = 0; j < 8; j++) s[j] = make_float4(0.f, 0.f, 0.f, 0.f);
        #pragma unroll
        for (int kb = 0; kb < 2; kb++) {
            #pragma unroll
            for (int p = 0; p < 4; p++) {
                uint32_t bf0, bf1, bf2, bf3;
                ldsm4(bf0, bf1, bf2, bf3,
                      sK + ((p * 16 + b_r) * 20 + 8 * kb + b_chi * 4) * 4);
                uint32_t b01[2] = { bf0, bf1 };
                uint32_t b23[2] = { bf2, bf3 };
                mma16(s[2 * p],     qf[kb], b01);
                mma16(s[2 * p + 1], qf[kb], b23);
            }
        }

        if (kv0 + 63 > warp_min_row + VKV || kv0 + 63 >= KVLEN) {
            #pragma unroll
            for (int j = 0; j < 8; j++) {
                int c0 = kv0 + j * 8 + 2 * tg;
                int c1 = c0 + 1;
                s[j].x = (c0 <= row_lo + VKV && c0 < KVLEN) ? s[j].x : -INFINITY;
                s[j].y = (c1 <= row_lo + VKV && c1 < KVLEN) ? s[j].y : -INFINITY;
                s[j].z = (c0 <= row_hi + VKV && c0 < KVLEN) ? s[j].z : -INFINITY;
                s[j].w = (c1 <= row_hi + VKV && c1 < KVLEN) ? s[j].w : -INFINITY;
            }
        }

        float mx_lo = -INFINITY, mx_hi = -INFINITY;
        #pragma unroll
        for (int j = 0; j < 8; j++) {
            mx_lo = fmaxf(mx_lo, fmaxf(s[j].x, s[j].y));
            mx_hi = fmaxf(mx_hi, fmaxf(s[j].z, s[j].w));
        }
        mx_lo = fmaxf(mx_lo, __shfl_xor_sync(FULLM, mx_lo, 1));
        mx_lo = fmaxf(mx_lo, __shfl_xor_sync(FULLM, mx_lo, 2));
        mx_hi = fmaxf(mx_hi, __shfl_xor_sync(FULLM, mx_hi, 1));
        mx_hi = fmaxf(mx_hi, __shfl_xor_sync(FULLM, mx_hi, 2));
        float mn_lo = fmaxf(m_lo, mx_lo);
        float mn_hi = fmaxf(m_hi, mx_hi);
        float corr_lo = ex2(m_lo - mn_lo);
        float corr_hi = ex2(m_hi - mn_hi);

        float ps_lo = 0.f, ps_hi = 0.f;
        #pragma unroll
        for (int j = 0; j < 8; j++) {
            s[j].x = ex2(s[j].x - mn_lo);
            s[j].y = ex2(s[j].y - mn_lo);
            s[j].z = ex2(s[j].z - mn_hi);
            s[j].w = ex2(s[j].w - mn_hi);
            ps_lo += s[j].x + s[j].y;
            ps_hi += s[j].z + s[j].w;
        }
        ps_lo += __shfl_xor_sync(FULLM, ps_lo, 1);
        ps_lo += __shfl_xor_sync(FULLM, ps_lo, 2);
        ps_hi += __shfl_xor_sync(FULLM, ps_hi, 1);
        ps_hi += __shfl_xor_sync(FULLM, ps_hi, 2);
        l_lo = l_lo * corr_lo + ps_lo;
        l_hi = l_hi * corr_hi + ps_hi;
        m_lo = mn_lo; m_hi = mn_hi;
        #pragma unroll
        for (int j = 0; j < 8; j++) {
            z[j].x *= corr_lo; z[j].y *= corr_lo;
            z[j].z *= corr_hi; z[j].w *= corr_hi;
        }

        // Z += P V : P A-frags from S C-frags (packs); V B-frags via ldmatrix
        #pragma unroll
        for (int kb = 0; kb < 4; kb++) {
            uint32_t af[4];
            af[0] = packh2(s[2 * kb].x,     s[2 * kb].y);
            af[1] = packh2(s[2 * kb].z,     s[2 * kb].w);
            af[2] = packh2(s[2 * kb + 1].x, s[2 * kb + 1].y);
            af[3] = packh2(s[2 * kb + 1].z, s[2 * kb + 1].w);
            #pragma unroll
            for (int p = 0; p < 4; p++) {
                uint32_t bf0, bf1, bf2, bf3;
                ldsm4(bf0, bf1, bf2, bf3,
                      sV + ((p * 16 + b_r) * 36 + 8 * kb + b_chi * 4) * 4);
                uint32_t b01[2] = { bf0, bf1 };
                uint32_t b23[2] = { bf2, bf3 };
                mma16(z[2 * p],     af, b01);
                mma16(z[2 * p + 1], af, b23);
            }
        }
    }

    float li_lo = 1.f / l_lo;
    float li_hi = 1.f / l_hi;
    __half* zlo = g_zh + ((size_t)b * SEQ + row_lo) * NOV + h * RATIO;
    __half* zhi = g_zh + ((size_t)b * SEQ + row_hi) * NOV + h * RATIO;
    #pragma unroll
    for (int j = 0; j < 8; j++) {
        int col = j * 8 + 2 * tg;
        *(uint32_t*)&zlo[col] = packh2(z[j].x * li_lo, z[j].y * li_lo);
        *(uint32_t*)&zhi[col] = packh2(z[j].z * li_hi, z[j].w * li_hi);
    }
}

// ---------------- output GEMM: fp16 mma, BK=64 XOR-swizzled, 3-stage. BM=64, BN=128 ----
__global__ void __launch_bounds__(256, 2) out_gemm_kernel(float* __restrict__ out)
{
    extern __shared__ uint32_t dsm[];
    uint32_t smb = (uint32_t)__cvta_generic_to_shared(dsm);

    int n0 = blockIdx.x * 128, r0 = blockIdx.y * 64;
    int t = threadIdx.x;
    int w = t >> 5, lane = t & 31;
    int g = lane >> 2, tg = lane & 3;
    int wm = w >> 1, wn = w & 1;

    float4 acc[8];
    #pragma unroll
    for (int j = 0; j < 8; j++) acc[j] = make_float4(0.f, 0.f, 0.f, 0.f);

    const __half* Abase = g_zh + (size_t)r0 * NOV;
    const __half* Bbase = g_woh + (size_t)n0 * NOV;

    int a_r = lane & 15;
    int a_chi = (lane >> 4) & 1;
    int b_r = (lane & 7) + ((lane & 16) ? 8 : 0);
    int b_chi = (lane >> 3) & 1;

    auto issue = [&](int kt) {
        int s = (kt % 3) * 6144;
        int k0 = kt * 64;
        #pragma unroll
        for (int i = 0; i < 2; i++) {
            int idx = t + i * 256;
            int row = idx >> 3, c = idx & 7;
            int sw = ((c ^ (row & 7)) << 2);
            cp_async16(smb + (s + row * 32 + sw) * 4,
                       Abase + (size_t)row * NOV + k0 + c * 8, 16);
        }
        #pragma unroll
        for (int i = 0; i < 4; i++) {
            int idx = t + i * 256;
            int row = idx >> 3, c = idx & 7;
            int sw = ((c ^ (row & 7)) << 2);
            cp_async16(smb + (s + 2048 + row * 32 + sw) * 4,
                       Bbase + (size_t)row * NOV + k0 + c * 8, 16);
        }
        asm volatile("cp.async.commit_group;" ::: "memory");
    };

    issue(0); issue(1);
    for (int kt = 0; kt < 32; kt++) {
        if (kt < 31) asm volatile("cp.async.wait_group 1;" ::: "memory");
        else         asm volatile("cp.async.wait_group 0;" ::: "memory");
        __syncthreads();
        if (kt + 2 < 32) issue(kt + 2);

        uint32_t sA = smb + ((kt % 3) * 6144) * 4;
        uint32_t sB = sA + 2048 * 4;
        #pragma unroll
        for (int kb = 0; kb < 4; kb++) {
            uint32_t af[4];
            {
                int row = wm * 16 + a_r;
                int c = kb * 2 + a_chi;
                ldsm4(af[0], af[1], af[2], af[3],
                      sA + (row * 32 + ((c ^ (row & 7)) << 2)) * 4);
            }
            #pragma unroll
            for (int p = 0; p < 4; p++) {
                int row = wn * 64 + p * 16 + b_r;
                int c = kb * 2 + b_chi;
                uint32_t bf0, bf1, bf2, bf3;
                ldsm4(bf0, bf1, bf2, bf3,
                      sB + (row * 32 + ((c ^ (row & 7)) << 2)) * 4);
                uint32_t b01[2] = { bf0, bf1 };
                uint32_t b23[2] = { bf2, bf3 };
                mma16(acc[2 * p],     af, b01);
                mma16(acc[2 * p + 1], af, b23);
            }
        }
    }

    int row0 = r0 + wm * 16 + g;
    #pragma unroll
    for (int j = 0; j < 8; j++) {
        int n = n0 + wn * 64 + j * 8 + tg * 2;
        *(float2*)&out[(size_t)row0 * DMODEL + n] = make_float2(acc[j].x, acc[j].y);
        *(float2*)&out[(size_t)(row0 + 8) * DMODEL + n] = make_float2(acc[j].z, acc[j].w);
    }
}

// ---------------- launch ----------------
extern "C" void kernel_launch(void* const* d_in, const int* in_sizes, int n_in,
                              void* d_out, int out_size)
{
    const float* resid = (const float*)d_in[0];
    const float* Wq    = (const float*)d_in[1];
    const float* Wk    = (const float*)d_in[2];
    const float* Wv    = (const float*)d_in[3];
    const float* Wo    = (const float*)d_in[4];
    const float* bq    = (const float*)d_in[5];
    const float* bk    = (const float*)d_in[6];
    const float* bv    = (const float*)d_in[7];
    const float* vk    = (const float*)d_in[8];
    const float* vv    = (const float*)d_in[9];
    float* out = (float*)d_out;

    const int ATTN_SMEM = (3 * 1280 + 3 * 2304) * 4;   // 43008
    const int QKV_SMEM  = 3 * 8192 * 4;                // 98304
    const int OUT_SMEM  = 3 * 6144 * 4;                // 73728
    static int smem_set = 0;
    if (!smem_set) {
        cudaFuncSetAttribute(attn_mma_kernel,
                             cudaFuncAttributeMaxDynamicSharedMemorySize, ATTN_SMEM);
        cudaFuncSetAttribute(qkv_gemm_kernel,
                             cudaFuncAttributeMaxDynamicSharedMemorySize, QKV_SMEM);
        cudaFuncSetAttribute(out_gemm_kernel,
                             cudaFuncAttributeMaxDynamicSharedMemorySize, OUT_SMEM);
        smem_set = 1;
    }

    prep_kernel<<<2048, 256>>>(resid, Wv, vk, vv, Wq, Wk);
    qkv_gemm_kernel<<<dim3(33, 16), 256, QKV_SMEM>>>(bq, bk, bv, Wo);
    attn_mma_kernel<<<dim3(8, 32, 2), 256, ATTN_SMEM>>>();
    out_gemm_kernel<<<dim3(8, 32), 256, OUT_SMEM>>>(out);
}

// round 17
// speedup vs baseline: 1.3816x; 1.0578x over previous
#include <cuda_runtime.h>
#include <cuda_fp16.h>
#include <math.h>
#include <stdint.h>

#define SEQ    1024
#define DMODEL 1024
#define NQK    32
#define DQK    32
#define NOV    2048
#define BATCH  2
#define VKV    16
#define KVLEN  (SEQ + VKV)   /* 1040 */
#define KVPAD  1088          /* padded kv pitch for g_vh */
#define RATIO  (NOV / NQK)   /* 64 */
#define FULLM  0xFFFFFFFFu

// ---------------- scratch (static device globals; no allocation) ----------------
__device__ __half g_qh[(size_t)BATCH * NQK * SEQ   * DQK];   // [b][h][s][d], pre-scaled log2e/sqrt(32)
__device__ __half g_kh[(size_t)BATCH * NQK * KVLEN * DQK];   // [b][h][kv][d]
__device__ __half g_vh[(size_t)BATCH * NOV * KVPAD];         // [b][n][kv]  (transposed, padded)
__device__ __half g_zh[(size_t)BATCH * SEQ * NOV];           // [bs][n]
__device__ __half g_xh[(size_t)BATCH * SEQ * DMODEL];        // resid as half [m][k]
__device__ __half g_bh[(size_t)4096 * DMODEL];               // [Wq^T | Wk^T | Wv] as [n][k]
__device__ __half g_woh[(size_t)DMODEL * NOV];               // Wo^T as [n][k]
__device__ float  g_sin[SEQ * 16];
__device__ float  g_cos[SEQ * 16];

// ---------------- helpers ----------------
__device__ __forceinline__ uint32_t packh2(float lo, float hi) {
    __half2 h = __floats2half2_rn(lo, hi);
    return *(uint32_t*)&h;
}
__device__ __forceinline__ float ex2(float x) {
    float y;
    asm("ex2.approx.f32 %0, %1;" : "=f"(y) : "f"(x));
    return y;
}
__device__ __forceinline__ void mma16(float4& d, const uint32_t* a, const uint32_t* b) {
    asm volatile(
        "mma.sync.aligned.m16n8k16.row.col.f32.f16.f16.f32 "
        "{%0,%1,%2,%3}, {%4,%5,%6,%7}, {%8,%9}, {%0,%1,%2,%3};\n"
        : "+f"(d.x), "+f"(d.y), "+f"(d.z), "+f"(d.w)
        : "r"(a[0]), "r"(a[1]), "r"(a[2]), "r"(a[3]), "r"(b[0]), "r"(b[1]));
}
__device__ __forceinline__ void cp_async16(uint32_t dst_smem, const void* src, int src_bytes) {
    asm volatile("cp.async.cg.shared.global [%0], [%1], 16, %2;"
                 :: "r"(dst_smem), "l"(src), "r"(src_bytes));
}
__device__ __forceinline__ void ldsm4(uint32_t& r0, uint32_t& r1, uint32_t& r2, uint32_t& r3,
                                      uint32_t addr) {
    asm volatile("ldmatrix.sync.aligned.m8n8.x4.shared.b16 {%0,%1,%2,%3}, [%4];"
                 : "=r"(r0), "=r"(r1), "=r"(r2), "=r"(r3) : "r"(addr));
}

// ---------------- prep: converts + rotary + virtual kv  AND  Wq/Wk transpose ---------
__global__ void __launch_bounds__(256) prep_kernel(
    const float* __restrict__ resid, const float* __restrict__ Wv,
    const float* __restrict__ vk, const float* __restrict__ vv,
    const float* __restrict__ Wq, const float* __restrict__ Wk)
{
    int bid = blockIdx.x;
    int t = threadIdx.x;
    if (bid < 1024) {
        int i = bid * 256 + t;
        size_t base = (size_t)i * 8;
        float4 a0 = *(const float4*)(resid + base);
        float4 a1 = *(const float4*)(resid + base + 4);
        *(uint4*)&g_xh[base] = make_uint4(packh2(a0.x, a0.y), packh2(a0.z, a0.w),
                                          packh2(a1.x, a1.y), packh2(a1.z, a1.w));
        float4 b0 = *(const float4*)(Wv + base);
        float4 b1 = *(const float4*)(Wv + base + 4);
        *(uint4*)&g_bh[(size_t)2048 * DMODEL + base] =
            make_uint4(packh2(b0.x, b0.y), packh2(b0.z, b0.w),
                       packh2(b1.x, b1.y), packh2(b1.z, b1.w));
        if (i < SEQ * 16) {
            int pos = i >> 4, jm = i & 15;
            float freq = powf(10000.0f, (float)jm * (1.0f / 16.0f));
            float ang = (float)pos / freq;
            g_sin[i] = sinf(ang);
            g_cos[i] = cosf(ang);
        }
        if (i < BATCH * NQK * VKV * DQK) {
            int d  = i & 31;
            int tt = (i >> 5) & 15;
            int h  = (i >> 9) & 31;
            int b  = i >> 14;
            g_kh[(((size_t)b * NQK + h) * KVLEN + SEQ + tt) * DQK + d] =
                __float2half(vk[((size_t)tt * NQK + h) * DQK + d]);
        }
        if (i < BATCH * NOV * 64) {
            int c = 1024 + (i & 63);
            int n = (i >> 6) & 2047;
            int b = i >> 17;
            float val = (c < KVLEN) ? vv[(size_t)(c - SEQ) * NOV + n] : 0.f;
            g_vh[((size_t)b * NOV + n) * KVPAD + c] = __float2half(val);
        }
    } else {
        __shared__ float sm[64][33];
        int b2 = bid - 1024;
        int z  = b2 >> 9;              // 0=Wq, 1=Wk
        int h  = (b2 >> 4) & 31;
        int m0 = (b2 & 15) * 64;
        const float* W = z ? Wk : Wq;
        #pragma unroll
        for (int i = 0; i < 2; i++) {
            int row = (t >> 3) + i * 32;
            int c4 = (t & 7) * 4;
            float4 v = *(const float4*)(W + ((size_t)h * 1024 + m0 + row) * 32 + c4);
            sm[row][c4] = v.x; sm[row][c4 + 1] = v.y;
            sm[row][c4 + 2] = v.z; sm[row][c4 + 3] = v.w;
        }
        __syncthreads();
        int d = t >> 3, mc = t & 7;
        __half h8[8];
        #pragma unroll
        for (int i = 0; i < 8; i++) h8[i] = __float2half(sm[mc * 8 + i][d]);
        *(uint4*)&g_bh[((size_t)z * 1024 + h * 32 + d) * DMODEL + m0 + mc * 8] =
            *(uint4*)h8;
    }
}

// ---------------- fused QKV GEMM; nt 0..3 = Wo transpose (front-loaded, 64 blocks) ----
// nt 4..11 -> Q, 12..19 -> K, 20..35 -> V.
__global__ void __launch_bounds__(256, 2) qkv_gemm_kernel(
    const float* __restrict__ bq, const float* __restrict__ bk,
    const float* __restrict__ bv, const float* __restrict__ Wo)
{
    extern __shared__ uint32_t dsm[];
    int nt = blockIdx.x;
    int t = threadIdx.x;

    if (nt < 4) {
        // Wo transpose: [k=2048][n=1024] f32 -> g_woh[n][k] half.
        // Block covers k slab [kb0, kb0+128) x n quarter [nt*256, nt*256+256) = 16 tiles.
        float (*Ts)[33] = (float(*)[33])dsm;
        int kb0 = blockIdx.y * 128;
        int nq0 = nt * 256;
        #pragma unroll 1
        for (int tt = 0; tt < 16; tt++) {
            int k0 = kb0 + (tt & 1) * 64;
            int n0 = nq0 + (tt >> 1) * 32;
            __syncthreads();
            #pragma unroll
            for (int i = 0; i < 2; i++) {
                int row = (t >> 3) + i * 32;
                int c4 = (t & 7) * 4;
                float4 v = *(const float4*)(Wo + (size_t)(k0 + row) * DMODEL + n0 + c4);
                Ts[row][c4] = v.x; Ts[row][c4 + 1] = v.y;
                Ts[row][c4 + 2] = v.z; Ts[row][c4 + 3] = v.w;
            }
            __syncthreads();
            int d = t >> 3, mc = t & 7;
            __half h8[8];
            #pragma unroll
            for (int i = 0; i < 8; i++) h8[i] = __float2half(Ts[mc * 8 + i][d]);
            *(uint4*)&g_woh[(size_t)(n0 + d) * NOV + k0 + mc * 8] = *(uint4*)h8;
        }
        return;
    }

    float (*Cs)[132] = (float(*)[132])dsm;
    __half* Ch = (__half*)dsm;
    uint32_t smb = (uint32_t)__cvta_generic_to_shared(dsm);

    int ng = nt - 4;                   // gemm n-tile 0..31
    int n0 = ng * 128;
    int r0 = blockIdx.y * 128;
    int region = (ng < 8) ? 0 : (ng < 16) ? 1 : 2;
    int cb = (region == 0) ? n0 : (region == 1) ? n0 - 1024 : n0 - 2048;
    int hbase = cb >> 5;

    int w = t >> 5, lane = t & 31;
    int g = lane >> 2, tg = lane & 3;
    int wm = w >> 1, wn = w & 1;

    float4 acc[2][8];
    #pragma unroll
    for (int i = 0; i < 2; i++)
        #pragma unroll
        for (int j = 0; j < 8; j++) acc[i][j] = make_float4(0.f, 0.f, 0.f, 0.f);

    const __half* Abase = g_xh + (size_t)r0 * DMODEL;
    const __half* Bbase = g_bh + (size_t)n0 * DMODEL;

    int a_r = lane & 15;
    int a_chi = (lane >> 4) & 1;
    int b_r = (lane & 7) + ((lane & 16) ? 8 : 0);
    int b_chi = (lane >> 3) & 1;

    auto issue = [&](int kt) {
        int s = (kt % 3) * 8192;
        int k0 = kt * 64;
        #pragma unroll
        for (int i = 0; i < 4; i++) {
            int idx = t + i * 256;
            int row = idx >> 3, c = idx & 7;
            int sw = ((c ^ (row & 7)) << 2);
            cp_async16(smb + (s + row * 32 + sw) * 4,
                       Abase + (size_t)row * DMODEL + k0 + c * 8, 16);
            cp_async16(smb + (s + 4096 + row * 32 + sw) * 4,
                       Bbase + (size_t)row * DMODEL + k0 + c * 8, 16);
        }
        asm volatile("cp.async.commit_group;" ::: "memory");
    };

    issue(0); issue(1);
    for (int kt = 0; kt < 16; kt++) {
        if (kt < 15) asm volatile("cp.async.wait_group 1;" ::: "memory");
        else         asm volatile("cp.async.wait_group 0;" ::: "memory");
        __syncthreads();
        if (kt + 2 < 16) issue(kt + 2);

        uint32_t sA = smb + ((kt % 3) * 8192) * 4;
        uint32_t sB = sA + 4096 * 4;
        #pragma unroll
        for (int kb = 0; kb < 4; kb++) {
            uint32_t af[2][4];
            #pragma unroll
            for (int i = 0; i < 2; i++) {
                int row = wm * 32 + i * 16 + a_r;
                int c = kb * 2 + a_chi;
                ldsm4(af[i][0], af[i][1], af[i][2], af[i][3],
                      sA + (row * 32 + ((c ^ (row & 7)) << 2)) * 4);
            }
            #pragma unroll
            for (int p = 0; p < 4; p++) {
                int row = wn * 64 + p * 16 + b_r;
                int c = kb * 2 + b_chi;
                uint32_t bf0, bf1, bf2, bf3;
                ldsm4(bf0, bf1, bf2, bf3,
                      sB + (row * 32 + ((c ^ (row & 7)) << 2)) * 4);
                uint32_t b01[2] = { bf0, bf1 };
                uint32_t b23[2] = { bf2, bf3 };
                mma16(acc[0][2 * p],     af[0], b01);
                mma16(acc[1][2 * p],     af[1], b01);
                mma16(acc[0][2 * p + 1], af[0], b23);
                mma16(acc[1][2 * p + 1], af[1], b23);
            }
        }
    }
    __syncthreads();

    if (region == 2) {
        int nv0 = cb;
        #pragma unroll
        for (int i = 0; i < 2; i++) {
            int rl = wm * 32 + i * 16 + g;
            #pragma unroll
            for (int j = 0; j < 8; j++) {
                int n = wn * 64 + j * 8 + tg * 2;
                float2 bvv = *(const float2*)(bv + nv0 + n);
                Ch[(size_t)n       * 136 + rl    ] = __float2half(acc[i][j].x + bvv.x);
                Ch[(size_t)(n + 1) * 136 + rl    ] = __float2half(acc[i][j].y + bvv.y);
                Ch[(size_t)n       * 136 + rl + 8] = __float2half(acc[i][j].z + bvv.x);
                Ch[(size_t)(n + 1) * 136 + rl + 8] = __float2half(acc[i][j].w + bvv.y);
            }
        }
        __syncthreads();
        int b = r0 >> 10, s0 = r0 & 1023;
        #pragma unroll
        for (int p = 0; p < 8; p++) {
            int idx = t + p * 256;
            int n = idx >> 4, c8 = (idx & 15) * 8;
            uint4 v = *(uint4*)&Ch[(size_t)n * 136 + c8];
            *(uint4*)&g_vh[((size_t)b * NOV + nv0 + n) * KVPAD + s0 + c8] = v;
        }
    } else {
        const float* bias = (region == 0) ? bq : bk;
        #pragma unroll
        for (int i = 0; i < 2; i++) {
            int rr = wm * 32 + i * 16 + g;
            #pragma unroll
            for (int j = 0; j < 8; j++) {
                int c = wn * 64 + j * 8 + tg * 2;
                float b0 = bias[cb + c];
                float b1 = bias[cb + c + 1];
                Cs[rr    ][c    ] = acc[i][j].x + b0;
                Cs[rr    ][c + 1] = acc[i][j].y + b1;
                Cs[rr + 8][c    ] = acc[i][j].z + b0;
                Cs[rr + 8][c + 1] = acc[i][j].w + b1;
            }
        }
        __syncthreads();

        const float qscale = 0.17677669529663687f * 1.4426950408889634f;  // log2e/sqrt(32)
        float sc = (region == 0) ? qscale : 1.f;
        #pragma unroll
        for (int p = 0; p < 2; p++) {
            int idx = t + p * 256;
            int r = idx >> 2, hh = idx & 3;
            int grow = r0 + r;
            int bb = grow >> 10, pos = grow & 1023;
            int h = hbase + hh;
            const float* base = &Cs[r][hh * 32];
            __half* dst = (region == 0)
                ? g_qh + (((size_t)bb * NQK + h) * SEQ   + pos) * DQK
                : g_kh + (((size_t)bb * NQK + h) * KVLEN + pos) * DQK;
            #pragma unroll
            for (int c = 0; c < 32; c++) {
                float val  = base[c];
                float flip = (c < 16) ? -base[c + 16] : base[c - 16];
                int jm = c & 15;
                float sn = g_sin[pos * 16 + jm];
                float cs = g_cos[pos * 16 + jm];
                dst[c] = __float2half((val * cs + flip * sn) * sc);
            }
        }
    }
}

// ---------------- attention: fp16 mma flash, 3-stage cp.async, ldmatrix frags --------
__global__ void __launch_bounds__(256, 2) attn_mma_kernel()
{
    extern __shared__ uint32_t smem[];
    uint32_t* Kb0 = smem;                  // per stage 1280 words
    uint32_t* Vb0 = smem + 3 * 1280;       // per stage 2304 words
    uint32_t smbK = (uint32_t)__cvta_generic_to_shared(Kb0);
    uint32_t smbV = (uint32_t)__cvta_generic_to_shared(Vb0);

    int qt = 7 - blockIdx.x;
    int h = blockIdx.y, b = blockIdx.z;
    int i0 = qt * 128;
    int t = threadIdx.x, w = t >> 5, lane = t & 31;
    int g = lane >> 2, tg = lane & 3;

    const __half* kbp = g_kh + ((size_t)b * NQK + h) * KVLEN * DQK;
    const __half* vbp = g_vh + ((size_t)b * NOV + h * RATIO) * KVPAD;

    uint32_t qf[2][4];
    {
        const __half* qb = g_qh + (((size_t)b * NQK + h) * SEQ + i0 + w * 16) * DQK;
        #pragma unroll
        for (int kb = 0; kb < 2; kb++) {
            qf[kb][0] = *(const uint32_t*)(qb + (size_t)g       * DQK + kb * 16 + 2 * tg);
            qf[kb][1] = *(const uint32_t*)(qb + (size_t)(g + 8) * DQK + kb * 16 + 2 * tg);
            qf[kb][2] = *(const uint32_t*)(qb + (size_t)g       * DQK + kb * 16 + 8 + 2 * tg);
            qf[kb][3] = *(const uint32_t*)(qb + (size_t)(g + 8) * DQK + kb * 16 + 8 + 2 * tg);
        }
    }

    float m_lo = -INFINITY, m_hi = -INFINITY, l_lo = 0.f, l_hi = 0.f;
    float4 z[8];
    #pragma unroll
    for (int j = 0; j < 8; j++) z[j] = make_float4(0.f, 0.f, 0.f, 0.f);

    int row_lo = i0 + w * 16 + g;
    int row_hi = row_lo + 8;
    int warp_min_row = i0 + w * 16;

    int jlim = i0 + 128 + VKV;
    if (jlim > KVLEN) jlim = KVLEN;
    int nch = (jlim + 63) >> 6;

    int b_r = (lane & 7) + ((lane & 16) ? 8 : 0);
    int b_chi = (lane >> 3) & 1;

    auto issue = [&](int ch) {
        int kv0 = ch << 6;
        int st = ch % 3;
        {
            int row = t >> 2, seg = t & 3;
            int gj = kv0 + row;
            int cg2 = gj < KVLEN ? gj : KVLEN - 1;
            cp_async16(smbK + (st * 1280 + row * 20 + seg * 4) * 4,
                       kbp + (size_t)cg2 * DQK + seg * 8, gj < KVLEN ? 16 : 0);
        }
        #pragma unroll
        for (int i = 0; i < 2; i++) {
            int idx = t + i * 256;
            int row = idx >> 3, seg = idx & 7;
            cp_async16(smbV + (st * 2304 + row * 36 + seg * 4) * 4,
                       vbp + (size_t)row * KVPAD + kv0 + seg * 8, 16);
        }
        asm volatile("cp.async.commit_group;" ::: "memory");
    };

    issue(0);
    if (nch > 1) issue(1);

    for (int ch = 0; ch < nch; ch++) {
        int kv0 = ch << 6;
        if (ch + 1 < nch) asm volatile("cp.async.wait_group 1;" ::: "memory");
        else              asm volatile("cp.async.wait_group 0;" ::: "memory");
        __syncthreads();
        if (ch + 2 < nch) issue(ch + 2);

        uint32_t sK = smbK + ((ch % 3) * 1280) * 4;
        uint32_t sV = smbV + ((ch % 3) * 2304) * 4;

        float4 s[8];
        #pragma unroll
        for (int j = 0; j < 8; j++) s[j] = make_float4(0.f, 0.f, 0.f, 0.f);
        #pragma unroll
        for (int kb = 0; kb < 2; kb++) {
            #pragma unroll
            for (int p = 0; p < 4; p++) {
                uint32_t bf0, bf1, bf2, bf3;
                ldsm4(bf0, bf1, bf2, bf3,
                      sK + ((p * 16 + b_r) * 20 + 8 * kb + b_chi * 4) * 4);
                uint32_t b01[2] = { bf0, bf1 };
                uint32_t b23[2] = { bf2, bf3 };
                mma16(s[2 * p],     qf[kb], b01);
                mma16(s[2 * p + 1], qf[kb], b23);
            }
        }

        if (kv0 + 63 > warp_min_row + VKV || kv0 + 63 >= KVLEN) {
            #pragma unroll
            for (int j = 0; j < 8; j++) {
                int c0 = kv0 + j * 8 + 2 * tg;
                int c1 = c0 + 1;
                s[j].x = (c0 <= row_lo + VKV && c0 < KVLEN) ? s[j].x : -INFINITY;
                s[j].y = (c1 <= row_lo + VKV && c1 < KVLEN) ? s[j].y : -INFINITY;
                s[j].z = (c0 <= row_hi + VKV && c0 < KVLEN) ? s[j].z : -INFINITY;
                s[j].w = (c1 <= row_hi + VKV && c1 < KVLEN) ? s[j].w : -INFINITY;
            }
        }

        float mx_lo = -INFINITY, mx_hi = -INFINITY;
        #pragma unroll
        for (int j = 0; j < 8; j++) {
            mx_lo = fmaxf(mx_lo, fmaxf(s[j].x, s[j].y));
            mx_hi = fmaxf(mx_hi, fmaxf(s[j].z, s[j].w));
        }
        mx_lo = fmaxf(mx_lo, __shfl_xor_sync(FULLM, mx_lo, 1));
        mx_lo = fmaxf(mx_lo, __shfl_xor_sync(FULLM, mx_lo, 2));
        mx_hi = fmaxf(mx_hi, __shfl_xor_sync(FULLM, mx_hi, 1));
        mx_hi = fmaxf(mx_hi, __shfl_xor_sync(FULLM, mx_hi, 2));
        float mn_lo = fmaxf(m_lo, mx_lo);
        float mn_hi = fmaxf(m_hi, mx_hi);
        float corr_lo = ex2(m_lo - mn_lo);
        float corr_hi = ex2(m_hi - mn_hi);

        float ps_lo = 0.f, ps_hi = 0.f;
        #pragma unroll
        for (int j = 0; j < 8; j++) {
            s[j].x = ex2(s[j].x - mn_lo);
            s[j].y = ex2(s[j].y - mn_lo);
            s[j].z = ex2(s[j].z - mn_hi);
            s[j].w = ex2(s[j].w - mn_hi);
            ps_lo += s[j].x + s[j].y;
            ps_hi += s[j].z + s[j].w;
        }
        ps_lo += __shfl_xor_sync(FULLM, ps_lo, 1);
        ps_lo += __shfl_xor_sync(FULLM, ps_lo, 2);
        ps_hi += __shfl_xor_sync(FULLM, ps_hi, 1);
        ps_hi += __shfl_xor_sync(FULLM, ps_hi, 2);
        l_lo = l_lo * corr_lo + ps_lo;
        l_hi = l_hi * corr_hi + ps_hi;
        m_lo = mn_lo; m_hi = mn_hi;
        #pragma unroll
        for (int j = 0; j < 8; j++) {
            z[j].x *= corr_lo; z[j].y *= corr_lo;
            z[j].z *= corr_hi; z[j].w *= corr_hi;
        }

        #pragma unroll
        for (int kb = 0; kb < 4; kb++) {
            uint32_t af[4];
            af[0] = packh2(s[2 * kb].x,     s[2 * kb].y);
            af[1] = packh2(s[2 * kb].z,     s[2 * kb].w);
            af[2] = packh2(s[2 * kb + 1].x, s[2 * kb + 1].y);
            af[3] = packh2(s[2 * kb + 1].z, s[2 * kb + 1].w);
            #pragma unroll
            for (int p = 0; p < 4; p++) {
                uint32_t bf0, bf1, bf2, bf3;
                ldsm4(bf0, bf1, bf2, bf3,
                      sV + ((p * 16 + b_r) * 36 + 8 * kb + b_chi * 4) * 4);
                uint32_t b01[2] = { bf0, bf1 };
                uint32_t b23[2] = { bf2, bf3 };
                mma16(z[2 * p],     af, b01);
                mma16(z[2 * p + 1], af, b23);
            }
        }
    }

    float li_lo = 1.f / l_lo;
    float li_hi = 1.f / l_hi;
    __half* zlo = g_zh + ((size_t)b * SEQ + row_lo) * NOV + h * RATIO;
    __half* zhi = g_zh + ((size_t)b * SEQ + row_hi) * NOV + h * RATIO;
    #pragma unroll
    for (int j = 0; j < 8; j++) {
        int col = j * 8 + 2 * tg;
        *(uint32_t*)&zlo[col] = packh2(z[j].x * li_lo, z[j].y * li_lo);
        *(uint32_t*)&zhi[col] = packh2(z[j].z * li_hi, z[j].w * li_hi);
    }
}

// ---------------- output GEMM: fp16 mma, BK=64 XOR-swizzled, 3-stage. BM=64, BN=128 ----
__global__ void __launch_bounds__(256, 2) out_gemm_kernel(float* __restrict__ out)
{
    extern __shared__ uint32_t dsm[];
    uint32_t smb = (uint32_t)__cvta_generic_to_shared(dsm);

    int n0 = blockIdx.x * 128, r0 = blockIdx.y * 64;
    int t = threadIdx.x;
    int w = t >> 5, lane = t & 31;
    int g = lane >> 2, tg = lane & 3;
    int wm = w >> 1, wn = w & 1;

    float4 acc[8];
    #pragma unroll
    for (int j = 0; j < 8; j++) acc[j] = make_float4(0.f, 0.f, 0.f, 0.f);

    const __half* Abase = g_zh + (size_t)r0 * NOV;
    const __half* Bbase = g_woh + (size_t)n0 * NOV;

    int a_r = lane & 15;
    int a_chi = (lane >> 4) & 1;
    int b_r = (lane & 7) + ((lane & 16) ? 8 : 0);
    int b_chi = (lane >> 3) & 1;

    auto issue = [&](int kt) {
        int s = (kt % 3) * 6144;
        int k0 = kt * 64;
        #pragma unroll
        for (int i = 0; i < 2; i++) {
            int idx = t + i * 256;
            int row = idx >> 3, c = idx & 7;
            int sw = ((c ^ (row & 7)) << 2);
            cp_async16(smb + (s + row * 32 + sw) * 4,
                       Abase + (size_t)row * NOV + k0 + c * 8, 16);
        }
        #pragma unroll
        for (int i = 0; i < 4; i++) {
            int idx = t + i * 256;
            int row = idx >> 3, c = idx & 7;
            int sw = ((c ^ (row & 7)) << 2);
            cp_async16(smb + (s + 2048 + row * 32 + sw) * 4,
                       Bbase + (size_t)row * NOV + k0 + c * 8, 16);
        }
        asm volatile("cp.async.commit_group;" ::: "memory");
    };

    issue(0); issue(1);
    for (int kt = 0; kt < 32; kt++) {
        if (kt < 31) asm volatile("cp.async.wait_group 1;" ::: "memory");
        else         asm volatile("cp.async.wait_group 0;" ::: "memory");
        __syncthreads();
        if (kt + 2 < 32) issue(kt + 2);

        uint32_t sA = smb + ((kt % 3) * 6144) * 4;
        uint32_t sB = sA + 2048 * 4;
        #pragma unroll
        for (int kb = 0; kb < 4; kb++) {
            uint32_t af[4];
            {
                int row = wm * 16 + a_r;
                int c = kb * 2 + a_chi;
                ldsm4(af[0], af[1], af[2], af[3],
                      sA + (row * 32 + ((c ^ (row & 7)) << 2)) * 4);
            }
            #pragma unroll
            for (int p = 0; p < 4; p++) {
                int row = wn * 64 + p * 16 + b_r;
                int c = kb * 2 + b_chi;
                uint32_t bf0, bf1, bf2, bf3;
                ldsm4(bf0, bf1, bf2, bf3,
                      sB + (row * 32 + ((c ^ (row & 7)) << 2)) * 4);
                uint32_t b01[2] = { bf0, bf1 };
                uint32_t b23[2] = { bf2, bf3 };
                mma16(acc[2 * p],     af, b01);
                mma16(acc[2 * p + 1], af, b23);
            }
        }
    }

    int row0 = r0 + wm * 16 + g;
    #pragma unroll
    for (int j = 0; j < 8; j++) {
        int n = n0 + wn * 64 + j * 8 + tg * 2;
        *(float2*)&out[(size_t)row0 * DMODEL + n] = make_float2(acc[j].x, acc[j].y);
        *(float2*)&out[(size_t)(row0 + 8) * DMODEL + n] = make_float2(acc[j].z, acc[j].w);
    }
}

// ---------------- launch ----------------
extern "C" void kernel_launch(void* const* d_in, const int* in_sizes, int n_in,
                              void* d_out, int out_size)
{
    const float* resid = (const float*)d_in[0];
    const float* Wq    = (const float*)d_in[1];
    const float* Wk    = (const float*)d_in[2];
    const float* Wv    = (const float*)d_in[3];
    const float* Wo    = (const float*)d_in[4];
    const float* bq    = (const float*)d_in[5];
    const float* bk    = (const float*)d_in[6];
    const float* bv    = (const float*)d_in[7];
    const float* vk    = (const float*)d_in[8];
    const float* vv    = (const float*)d_in[9];
    float* out = (float*)d_out;

    const int ATTN_SMEM = (3 * 1280 + 3 * 2304) * 4;   // 43008
    const int QKV_SMEM  = 3 * 8192 * 4;                // 98304
    const int OUT_SMEM  = 3 * 6144 * 4;                // 73728
    static int smem_set = 0;
    if (!smem_set) {
        cudaFuncSetAttribute(attn_mma_kernel,
                             cudaFuncAttributeMaxDynamicSharedMemorySize, ATTN_SMEM);
        cudaFuncSetAttribute(qkv_gemm_kernel,
                             cudaFuncAttributeMaxDynamicSharedMemorySize, QKV_SMEM);
        cudaFuncSetAttribute(out_gemm_kernel,
                             cudaFuncAttributeMaxDynamicSharedMemorySize, OUT_SMEM);
        smem_set = 1;
    }

    prep_kernel<<<2048, 256>>>(resid, Wv, vk, vv, Wq, Wk);
    qkv_gemm_kernel<<<dim3(36, 16), 256, QKV_SMEM>>>(bq, bk, bv, Wo);
    attn_mma_kernel<<<dim3(8, 32, 2), 256, ATTN_SMEM>>>();
    out_gemm_kernel<<<dim3(8, 32), 256, OUT_SMEM>>>(out);
}